// round 1
// baseline (speedup 1.0000x reference)
#include <cuda_runtime.h>
#include <math.h>

// ---------------- dims ----------------
#define BB   2
#define TT   2048
#define DD   768
#define NHH  12
#define NKVV 4
#define HDD  64
#define LL   6
#define VV   32000
#define DII  1536
#define NCC  64
#define CDD  128
#define ROWS (BB*TT)          // 4096
#define GATE_STRENGTH 0.001f

// ---------------- scratch (device globals; no allocation allowed) ----------------
__device__ float g_x [ROWS*DD];
__device__ float g_h [ROWS*DD];
__device__ float g_q [ROWS*NHH*HDD];
__device__ float g_k [ROWS*NKVV*HDD];
__device__ float g_v [ROWS*NKVV*HDD];
__device__ float g_ao[ROWS*NHH*HDD];
__device__ float g_b1[ROWS*DII];
__device__ float g_b2[ROWS*DII];
__device__ float g_cv[BB*10];
__device__ float g_tw[BB*3];
__device__ int   g_ti[BB*3];

// ---------------- helpers ----------------
__device__ __forceinline__ float block_reduce_sum_256(float v) {
    __shared__ float red[8];
    int t = threadIdx.x;
    #pragma unroll
    for (int off = 16; off; off >>= 1) v += __shfl_xor_sync(0xffffffffu, v, off);
    if ((t & 31) == 0) red[t >> 5] = v;
    __syncthreads();
    float tot = 0.f;
    #pragma unroll
    for (int i = 0; i < 8; i++) tot += red[i];
    return tot;
}

// ---------------- embedding ----------------
__global__ void embed_kernel(const int* __restrict__ idx,
                             const float* __restrict__ emb,
                             float* __restrict__ x) {
    long i = (long)blockIdx.x * blockDim.x + threadIdx.x;
    if (i < (long)ROWS * DD) {
        long r = i / DD, c = i % DD;
        x[i] = emb[(long)idx[r] * DD + c];
    }
}

// ---------------- consciousness vector (tiny MLP) ----------------
__global__ void cv_kernel(const float* __restrict__ cs,
                          const float* __restrict__ w1, const float* __restrict__ b1,
                          const float* __restrict__ w2, const float* __restrict__ b2,
                          float* __restrict__ cv) {
    __shared__ float pooled[BB][CDD];
    __shared__ float h1[BB][64];
    int t = threadIdx.x;  // 256 threads
    {
        int b = t / CDD, c = t % CDD;   // 2*128 = 256 exact
        float s = 0.f;
        for (int n = 0; n < NCC; n++)
            s += cs[((long)b * NCC + n) * CDD + c];
        pooled[b][c] = s * (1.f / NCC);
    }
    __syncthreads();
    if (t < BB * 64) {
        int b = t / 64, j = t % 64;
        float z = b1[j];
        for (int c = 0; c < CDD; c++) z += pooled[b][c] * w1[c * 64 + j];
        // jax.nn.gelu approximate=True (tanh form)
        float z3 = z * z * z;
        h1[b][j] = 0.5f * z * (1.f + tanhf(0.7978845608028654f * (z + 0.044715f * z3)));
    }
    __syncthreads();
    if (t < BB * 10) {
        int b = t / 10, i = t % 10;
        float z = b2[i];
        for (int j = 0; j < 64; j++) z += h1[b][j] * w2[j * 10 + i];
        cv[b * 10 + i] = 1.f / (1.f + expf(-z));
    }
}

// ---------------- RMSNorm (row per block, 256 threads) ----------------
__global__ void __launch_bounds__(256) rms_kernel(const float* __restrict__ x,
                                                  const float* __restrict__ w,
                                                  float* __restrict__ o) {
    int row = blockIdx.x, t = threadIdx.x;
    const float* xr = x + (long)row * DD;
    float v0 = xr[t], v1 = xr[t + 256], v2 = xr[t + 512];
    float tot = block_reduce_sum_256(v0 * v0 + v1 * v1 + v2 * v2);
    float s = rsqrtf(tot * (1.f / DD) + 1e-6f);
    float* orow = o + (long)row * DD;
    orow[t]       = v0 * s * w[t];
    orow[t + 256] = v1 * s * w[t + 256];
    orow[t + 512] = v2 * s * w[t + 512];
}

// ---------------- SwiGLU (+ optional tension) ----------------
__global__ void __launch_bounds__(256) swiglu_kernel(const float* __restrict__ g,
                                                     const float* __restrict__ u,
                                                     float* __restrict__ hid,
                                                     float* __restrict__ tension) {
    int row = blockIdx.x, t = threadIdx.x;
    const float* gr = g + (long)row * DII;
    const float* ur = u + (long)row * DII;
    float* hr = hid + (long)row * DII;
    float sum = 0.f;
    #pragma unroll
    for (int j = 0; j < 6; j++) {
        int c = t + j * 256;
        float a = gr[c], bv = ur[c];
        float hv = (a / (1.f + __expf(-a))) * bv;   // silu(a) * b
        hr[c] = hv;
        sum += hv;
    }
    if (tension) {
        float tot = block_reduce_sum_256(sum);
        if (t == 0) tension[row] = tanhf(tot * (1.f / DII));
    }
}

// ---------------- consciousness-state residual add ----------------
__global__ void __launch_bounds__(256) csadd_kernel(float* __restrict__ x,
                                                    const float* __restrict__ tension,
                                                    const float* __restrict__ tw) {
    int row = blockIdx.x, t = threadIdx.x;
    float ten = tension[row] * GATE_STRENGTH;
    float* xr = x + (long)row * DD;
    xr[t]       += ten * tw[t];
    xr[t + 256] += ten * tw[t + 256];
    xr[t + 512] += ten * tw[t + 512];
}

// ---------------- router: softmax + top-3 + renorm (per batch elem) ----------------
__global__ void router_kernel(const float* __restrict__ cv,
                              const float* __restrict__ W,
                              const float* __restrict__ bias,
                              float* __restrict__ tw, int* __restrict__ ti) {
    int b = threadIdx.x;
    if (b >= BB) return;
    float lg[10];
    float mx = -1e30f;
    for (int i = 0; i < 10; i++) {
        float z = bias[i];
        for (int j = 0; j < 10; j++) z += cv[b * 10 + j] * W[j * 10 + i];
        lg[i] = z;
        mx = fmaxf(mx, z);
    }
    float se = 0.f;
    for (int i = 0; i < 10; i++) { lg[i] = expf(lg[i] - mx); se += lg[i]; }
    for (int i = 0; i < 10; i++) lg[i] /= se;
    float wsum = 0.f;
    for (int kk = 0; kk < 3; kk++) {
        int bi = 0; float bv = -1.f;
        for (int i = 0; i < 10; i++) if (lg[i] > bv) { bv = lg[i]; bi = i; }
        ti[b * 3 + kk] = bi; tw[b * 3 + kk] = bv; wsum += bv;
        lg[bi] = -2.f;
    }
    for (int kk = 0; kk < 3; kk++) tw[b * 3 + kk] /= wsum;
}

// ---------------- flash-style causal attention (fp32, GQA) ----------------
// grid (T/64, NH, B), 64 threads; thread owns one query row (q + acc in registers).
__global__ void __launch_bounds__(64) attn_kernel(const float* __restrict__ q,
                                                  const float* __restrict__ k,
                                                  const float* __restrict__ v,
                                                  float* __restrict__ o) {
    const int q0 = blockIdx.x * 64;
    const int h  = blockIdx.y;
    const int b  = blockIdx.z;
    const int t  = threadIdx.x;
    const int qg = q0 + t;
    const int kvh = h / (NHH / NKVV);

    __shared__ float Ks[64][64];
    __shared__ float Vs[64][64];

    float qreg[64], acc[64];
    const float* qp = q + ((long)(b * TT + qg) * NHH + h) * HDD;
    #pragma unroll
    for (int d = 0; d < 64; d++) { qreg[d] = qp[d]; acc[d] = 0.f; }
    float lsum = 0.f;

    for (int s0 = 0; s0 <= q0; s0 += 64) {
        __syncthreads();
        #pragma unroll 8
        for (int r = 0; r < 64; r++) {
            long base = ((long)(b * TT + s0 + r) * NKVV + kvh) * HDD + t;
            Ks[r][t] = k[base];
            Vs[r][t] = v[base];
        }
        __syncthreads();
        int kmax = min(64, qg - s0 + 1);
        for (int kk = 0; kk < kmax; kk++) {
            float s = 0.f;
            #pragma unroll
            for (int d = 0; d < 64; d++) s += qreg[d] * Ks[kk][d];
            // activations here are small (|s| << 80): exp without max-shift is exact
            float p = __expf(s * 0.125f);
            lsum += p;
            #pragma unroll
            for (int d = 0; d < 64; d++) acc[d] += p * Vs[kk][d];
        }
    }
    float inv = 1.f / lsum;
    float* op = o + ((long)(b * TT + qg) * NHH + h) * HDD;
    #pragma unroll
    for (int d = 0; d < 64; d++) op[d] = acc[d] * inv;
}

// ---------------- SGEMM: C(MxN) = [C +] alpha * A(MxK) @ B / B^T ----------------
// 128x128 tile, BK=8, 8x8 per thread, 256 threads. Optional per-batch expert
// weight indirection (ti) and per-batch scaling (twp) resolved on-device.
template<bool ACC, bool TRANSB>
__global__ void __launch_bounds__(256) gemm_kernel(
    const float* __restrict__ A, const float* __restrict__ B, float* __restrict__ C,
    int M, int N, int K,
    const int* __restrict__ ti, const float* __restrict__ twp, int kexp, long estride)
{
    const int bx = blockIdx.x, by = blockIdx.y;
    float alpha = 1.f;
    if (ti) {
        int b = (by * 128) / TT;                 // rows of a tile never straddle batches
        B += (long)ti[b * 3 + kexp] * estride;
        if (twp) alpha = twp[b * 3 + kexp];
    }
    __shared__ float As[8][128];
    __shared__ float Bs[8][128];
    const int tid = threadIdx.x;
    const int tr = tid / 16, tc = tid % 16;
    const int rowA = tid / 2, colA = (tid % 2) * 4;

    float acc[8][8];
    #pragma unroll
    for (int i = 0; i < 8; i++)
        #pragma unroll
        for (int j = 0; j < 8; j++) acc[i][j] = 0.f;

    const float* Abase = A + (long)(by * 128) * K;
    for (int k0 = 0; k0 < K; k0 += 8) {
        float4 a4 = *(const float4*)(Abase + (long)rowA * K + k0 + colA);
        As[colA + 0][rowA] = a4.x; As[colA + 1][rowA] = a4.y;
        As[colA + 2][rowA] = a4.z; As[colA + 3][rowA] = a4.w;
        if (TRANSB) {
            int rB = tid / 2, cB = (tid % 2) * 4;   // rB: n-index, cB: k-index
            float4 b4 = *(const float4*)(B + (long)(bx * 128 + rB) * K + k0 + cB);
            Bs[cB + 0][rB] = b4.x; Bs[cB + 1][rB] = b4.y;
            Bs[cB + 2][rB] = b4.z; Bs[cB + 3][rB] = b4.w;
        } else {
            int rB = tid / 32, cB = (tid % 32) * 4;
            float4 b4 = *(const float4*)(B + (long)(k0 + rB) * N + bx * 128 + cB);
            *(float4*)&Bs[rB][cB] = b4;
        }
        __syncthreads();
        #pragma unroll
        for (int kk = 0; kk < 8; kk++) {
            float ra[8], rb[8];
            *(float4*)&ra[0] = *(const float4*)&As[kk][tr * 8];
            *(float4*)&ra[4] = *(const float4*)&As[kk][tr * 8 + 4];
            *(float4*)&rb[0] = *(const float4*)&Bs[kk][tc * 8];
            *(float4*)&rb[4] = *(const float4*)&Bs[kk][tc * 8 + 4];
            #pragma unroll
            for (int i = 0; i < 8; i++)
                #pragma unroll
                for (int j = 0; j < 8; j++)
                    acc[i][j] += ra[i] * rb[j];
        }
        __syncthreads();
    }
    #pragma unroll
    for (int i = 0; i < 8; i++) {
        long r = (long)(by * 128 + tr * 8 + i);
        float* crow = C + r * N + bx * 128 + tc * 8;
        #pragma unroll
        for (int j = 0; j < 8; j++) {
            float vv = acc[i][j] * alpha;
            if (ACC) crow[j] += vv; else crow[j] = vv;
        }
    }
}

// ---------------- launch ----------------
extern "C" void kernel_launch(void* const* d_in, const int* in_sizes, int n_in,
                              void* d_out, int out_size) {
    const int*   idx       = (const int*)  d_in[0];
    const float* cons      = (const float*)d_in[1];
    const float* tok_emb   = (const float*)d_in[2];
    const float* head_g    = (const float*)d_in[3];
    const float* cv_w1     = (const float*)d_in[4];
    const float* cv_b1     = (const float*)d_in[5];
    const float* cv_w2     = (const float*)d_in[6];
    const float* cv_b2     = (const float*)d_in[7];
    const float* tension_w = (const float*)d_in[8];
    const float* ln_attn   = (const float*)d_in[9];
    const float* ln_pf     = (const float*)d_in[10];
    const float* ln_moe    = (const float*)d_in[11];
    const float* ln_f      = (const float*)d_in[12];
    const float* wq        = (const float*)d_in[13];
    const float* wk        = (const float*)d_in[14];
    const float* wv        = (const float*)d_in[15];
    const float* wo        = (const float*)d_in[16];
    const float* pf_gate   = (const float*)d_in[17];
    const float* pf_up     = (const float*)d_in[18];
    const float* pf_down   = (const float*)d_in[19];
    const float* e_gate    = (const float*)d_in[20];
    const float* e_up      = (const float*)d_in[21];
    const float* e_down    = (const float*)d_in[22];
    const float* router_w  = (const float*)d_in[23];
    const float* router_b  = (const float*)d_in[24];
    float* out = (float*)d_out;

    float *xp, *hp, *qp, *kp, *vp, *aop, *b1p, *b2p, *cvp, *twp;
    int* tip;
    cudaGetSymbolAddress((void**)&xp,  g_x);
    cudaGetSymbolAddress((void**)&hp,  g_h);
    cudaGetSymbolAddress((void**)&qp,  g_q);
    cudaGetSymbolAddress((void**)&kp,  g_k);
    cudaGetSymbolAddress((void**)&vp,  g_v);
    cudaGetSymbolAddress((void**)&aop, g_ao);
    cudaGetSymbolAddress((void**)&b1p, g_b1);
    cudaGetSymbolAddress((void**)&b2p, g_b2);
    cudaGetSymbolAddress((void**)&cvp, g_cv);
    cudaGetSymbolAddress((void**)&twp, g_tw);
    cudaGetSymbolAddress((void**)&tip, g_ti);

    float* tens = out + (long)2 * ROWS * VV;   // output tail: tensions (L, B, T)

    embed_kernel<<<(ROWS * DD + 255) / 256, 256>>>(idx, tok_emb, xp);
    cv_kernel<<<1, 256>>>(cons, cv_w1, cv_b1, cv_w2, cv_b2, cvp);

    const dim3 g768 (DD  / 128, ROWS / 128);   // (6, 32)
    const dim3 g256 (256 / 128, ROWS / 128);   // (2, 32)
    const dim3 g1536(DII / 128, ROWS / 128);   // (12, 32)

    for (int l = 0; l < LL; l++) {
        // ---- attention block ----
        rms_kernel<<<ROWS, 256>>>(xp, ln_attn + (long)l * DD, hp);
        gemm_kernel<false, false><<<g768, 256>>>(hp, wq + (long)l * DD * 768, qp,
                                                 ROWS, 768, DD, nullptr, nullptr, 0, 0);
        gemm_kernel<false, false><<<g256, 256>>>(hp, wk + (long)l * DD * 256, kp,
                                                 ROWS, 256, DD, nullptr, nullptr, 0, 0);
        gemm_kernel<false, false><<<g256, 256>>>(hp, wv + (long)l * DD * 256, vp,
                                                 ROWS, 256, DD, nullptr, nullptr, 0, 0);
        attn_kernel<<<dim3(TT / 64, NHH, BB), 64>>>(qp, kp, vp, aop);
        gemm_kernel<true, false><<<g768, 256>>>(aop, wo + (long)l * 768 * DD, xp,
                                                ROWS, DD, 768, nullptr, nullptr, 0, 0);

        // ---- PureField FFN + tension ----
        rms_kernel<<<ROWS, 256>>>(xp, ln_pf + (long)l * DD, hp);
        gemm_kernel<false, false><<<g1536, 256>>>(hp, pf_gate + (long)l * DD * DII, b1p,
                                                  ROWS, DII, DD, nullptr, nullptr, 0, 0);
        gemm_kernel<false, false><<<g1536, 256>>>(hp, pf_up + (long)l * DD * DII, b2p,
                                                  ROWS, DII, DD, nullptr, nullptr, 0, 0);
        swiglu_kernel<<<ROWS, 256>>>(b1p, b2p, b1p, tens + (long)l * ROWS);
        gemm_kernel<true, false><<<g768, 256>>>(b1p, pf_down + (long)l * DII * DD, xp,
                                                ROWS, DD, DII, nullptr, nullptr, 0, 0);

        // ---- consciousness-state residual (from previous layer's tension) ----
        if (l > 0)
            csadd_kernel<<<ROWS, 256>>>(xp, tens + (long)(l - 1) * ROWS, tension_w);

        // ---- MoE (top-3 of 10, routed per batch element) ----
        rms_kernel<<<ROWS, 256>>>(xp, ln_moe + (long)l * DD, hp);
        router_kernel<<<1, 32>>>(cvp, router_w + (long)l * 100, router_b + (long)l * 10,
                                 twp, tip);
        for (int kk = 0; kk < 3; kk++) {
            gemm_kernel<false, false><<<g1536, 256>>>(hp, e_gate + (long)l * 10 * DD * DII,
                                                      b1p, ROWS, DII, DD,
                                                      tip, nullptr, kk, (long)DD * DII);
            gemm_kernel<false, false><<<g1536, 256>>>(hp, e_up + (long)l * 10 * DD * DII,
                                                      b2p, ROWS, DII, DD,
                                                      tip, nullptr, kk, (long)DD * DII);
            swiglu_kernel<<<ROWS, 256>>>(b1p, b2p, b1p, nullptr);
            gemm_kernel<true, false><<<g768, 256>>>(b1p, e_down + (long)l * 10 * DII * DD,
                                                    xp, ROWS, DD, DII,
                                                    tip, twp, kk, (long)DII * DD);
        }
    }

    // ---- final norm + tied heads ----
    rms_kernel<<<ROWS, 256>>>(xp, ln_f, hp);
    const dim3 gv(VV / 128, ROWS / 128);       // (250, 32)
    gemm_kernel<false, true><<<gv, 256>>>(hp, tok_emb, out,
                                          ROWS, VV, DD, nullptr, nullptr, 0, 0);
    gemm_kernel<false, true><<<gv, 256>>>(hp, head_g, out + (long)ROWS * VV,
                                          ROWS, VV, DD, nullptr, nullptr, 0, 0);
}

// round 2
// speedup vs baseline: 1.3666x; 1.3666x over previous
#include <cuda_runtime.h>
#include <cuda_bf16.h>
#include <math.h>

// ---------------- dims ----------------
#define BB   2
#define TT   2048
#define DD   768
#define NHH  12
#define NKVV 4
#define HDD  64
#define LL   6
#define VV   32000
#define DII  1536
#define NCC  64
#define CDD  128
#define ROWS (BB*TT)          // 4096
#define GATE_STRENGTH 0.001f

// ---------------- scratch (device globals; no allocation allowed) ----------------
__device__ float g_x [ROWS*DD];
__device__ float g_h [ROWS*DD];
__device__ float g_q [ROWS*NHH*HDD];
__device__ float g_k [ROWS*NKVV*HDD];
__device__ float g_v [ROWS*NKVV*HDD];
__device__ float g_ao[ROWS*NHH*HDD];
__device__ float g_b1[ROWS*DII];
__device__ float g_b2[ROWS*DII];
__device__ float g_cv[BB*10];
__device__ float g_tw[BB*3];
__device__ int   g_ti[BB*3];

// ---------------- helpers ----------------
__device__ __forceinline__ float block_reduce_sum_256(float v) {
    __shared__ float red[8];
    int t = threadIdx.x;
    #pragma unroll
    for (int off = 16; off; off >>= 1) v += __shfl_xor_sync(0xffffffffu, v, off);
    if ((t & 31) == 0) red[t >> 5] = v;
    __syncthreads();
    float tot = 0.f;
    #pragma unroll
    for (int i = 0; i < 8; i++) tot += red[i];
    return tot;
}

__device__ __forceinline__ void split2(float f0, float f1, unsigned& hi, unsigned& lo) {
    __nv_bfloat162 h = __floats2bfloat162_rn(f0, f1);
    float r0 = f0 - __bfloat162float(__low2bfloat16(h));
    float r1 = f1 - __bfloat162float(__high2bfloat16(h));
    __nv_bfloat162 l = __floats2bfloat162_rn(r0, r1);
    hi = *(unsigned*)&h;
    lo = *(unsigned*)&l;
}

__device__ __forceinline__ void mma16816(float* c, const unsigned* a, const unsigned* b) {
    asm volatile(
        "mma.sync.aligned.m16n8k16.row.col.f32.bf16.bf16.f32 "
        "{%0,%1,%2,%3}, {%4,%5,%6,%7}, {%8,%9}, {%0,%1,%2,%3};\n"
        : "+f"(c[0]), "+f"(c[1]), "+f"(c[2]), "+f"(c[3])
        : "r"(a[0]), "r"(a[1]), "r"(a[2]), "r"(a[3]), "r"(b[0]), "r"(b[1]));
}

// ---------------- embedding ----------------
__global__ void embed_kernel(const int* __restrict__ idx,
                             const float* __restrict__ emb,
                             float* __restrict__ x) {
    long i = (long)blockIdx.x * blockDim.x + threadIdx.x;
    if (i < (long)ROWS * DD) {
        long r = i / DD, c = i % DD;
        x[i] = emb[(long)idx[r] * DD + c];
    }
}

// ---------------- consciousness vector (tiny MLP) ----------------
__global__ void cv_kernel(const float* __restrict__ cs,
                          const float* __restrict__ w1, const float* __restrict__ b1,
                          const float* __restrict__ w2, const float* __restrict__ b2,
                          float* __restrict__ cv) {
    __shared__ float pooled[BB][CDD];
    __shared__ float h1[BB][64];
    int t = threadIdx.x;  // 256 threads
    {
        int b = t / CDD, c = t % CDD;
        float s = 0.f;
        for (int n = 0; n < NCC; n++)
            s += cs[((long)b * NCC + n) * CDD + c];
        pooled[b][c] = s * (1.f / NCC);
    }
    __syncthreads();
    if (t < BB * 64) {
        int b = t / 64, j = t % 64;
        float z = b1[j];
        for (int c = 0; c < CDD; c++) z += pooled[b][c] * w1[c * 64 + j];
        float z3 = z * z * z;
        h1[b][j] = 0.5f * z * (1.f + tanhf(0.7978845608028654f * (z + 0.044715f * z3)));
    }
    __syncthreads();
    if (t < BB * 10) {
        int b = t / 10, i = t % 10;
        float z = b2[i];
        for (int j = 0; j < 64; j++) z += h1[b][j] * w2[j * 10 + i];
        cv[b * 10 + i] = 1.f / (1.f + expf(-z));
    }
}

// ---------------- RMSNorm ----------------
__global__ void __launch_bounds__(256) rms_kernel(const float* __restrict__ x,
                                                  const float* __restrict__ w,
                                                  float* __restrict__ o) {
    int row = blockIdx.x, t = threadIdx.x;
    const float* xr = x + (long)row * DD;
    float v0 = xr[t], v1 = xr[t + 256], v2 = xr[t + 512];
    float tot = block_reduce_sum_256(v0 * v0 + v1 * v1 + v2 * v2);
    float s = rsqrtf(tot * (1.f / DD) + 1e-6f);
    float* orow = o + (long)row * DD;
    orow[t]       = v0 * s * w[t];
    orow[t + 256] = v1 * s * w[t + 256];
    orow[t + 512] = v2 * s * w[t + 512];
}

// ---------------- SwiGLU (+ optional tension) ----------------
__global__ void __launch_bounds__(256) swiglu_kernel(const float* __restrict__ g,
                                                     const float* __restrict__ u,
                                                     float* __restrict__ hid,
                                                     float* __restrict__ tension) {
    int row = blockIdx.x, t = threadIdx.x;
    const float* gr = g + (long)row * DII;
    const float* ur = u + (long)row * DII;
    float* hr = hid + (long)row * DII;
    float sum = 0.f;
    #pragma unroll
    for (int j = 0; j < 6; j++) {
        int c = t + j * 256;
        float a = gr[c], bv = ur[c];
        float hv = (a / (1.f + __expf(-a))) * bv;
        hr[c] = hv;
        sum += hv;
    }
    if (tension) {
        float tot = block_reduce_sum_256(sum);
        if (t == 0) tension[row] = tanhf(tot * (1.f / DII));
    }
}

// ---------------- consciousness-state residual add ----------------
__global__ void __launch_bounds__(256) csadd_kernel(float* __restrict__ x,
                                                    const float* __restrict__ tension,
                                                    const float* __restrict__ tw) {
    int row = blockIdx.x, t = threadIdx.x;
    float ten = tension[row] * GATE_STRENGTH;
    float* xr = x + (long)row * DD;
    xr[t]       += ten * tw[t];
    xr[t + 256] += ten * tw[t + 256];
    xr[t + 512] += ten * tw[t + 512];
}

// ---------------- router ----------------
__global__ void router_kernel(const float* __restrict__ cv,
                              const float* __restrict__ W,
                              const float* __restrict__ bias,
                              float* __restrict__ tw, int* __restrict__ ti) {
    int b = threadIdx.x;
    if (b >= BB) return;
    float lg[10];
    float mx = -1e30f;
    for (int i = 0; i < 10; i++) {
        float z = bias[i];
        for (int j = 0; j < 10; j++) z += cv[b * 10 + j] * W[j * 10 + i];
        lg[i] = z;
        mx = fmaxf(mx, z);
    }
    float se = 0.f;
    for (int i = 0; i < 10; i++) { lg[i] = expf(lg[i] - mx); se += lg[i]; }
    for (int i = 0; i < 10; i++) lg[i] /= se;
    float wsum = 0.f;
    for (int kk = 0; kk < 3; kk++) {
        int bi = 0; float bv = -1.f;
        for (int i = 0; i < 10; i++) if (lg[i] > bv) { bv = lg[i]; bi = i; }
        ti[b * 3 + kk] = bi; tw[b * 3 + kk] = bv; wsum += bv;
        lg[bi] = -2.f;
    }
    for (int kk = 0; kk < 3; kk++) tw[b * 3 + kk] /= wsum;
}

// ---------------- flash-style causal attention (fp32, GQA) ----------------
__global__ void __launch_bounds__(64) attn_kernel(const float* __restrict__ q,
                                                  const float* __restrict__ k,
                                                  const float* __restrict__ v,
                                                  float* __restrict__ o) {
    const int q0 = blockIdx.x * 64;
    const int h  = blockIdx.y;
    const int b  = blockIdx.z;
    const int t  = threadIdx.x;
    const int qg = q0 + t;
    const int kvh = h / (NHH / NKVV);

    __shared__ float Ks[64][64];
    __shared__ float Vs[64][64];

    float qreg[64], acc[64];
    const float* qp = q + ((long)(b * TT + qg) * NHH + h) * HDD;
    #pragma unroll
    for (int d = 0; d < 64; d++) { qreg[d] = qp[d]; acc[d] = 0.f; }
    float lsum = 0.f;

    for (int s0 = 0; s0 <= q0; s0 += 64) {
        __syncthreads();
        #pragma unroll 8
        for (int r = 0; r < 64; r++) {
            long base = ((long)(b * TT + s0 + r) * NKVV + kvh) * HDD + t;
            Ks[r][t] = k[base];
            Vs[r][t] = v[base];
        }
        __syncthreads();
        int kmax = min(64, qg - s0 + 1);
        for (int kk = 0; kk < kmax; kk++) {
            float s = 0.f;
            #pragma unroll
            for (int d = 0; d < 64; d++) s += qreg[d] * Ks[kk][d];
            float p = __expf(s * 0.125f);
            lsum += p;
            #pragma unroll
            for (int d = 0; d < 64; d++) acc[d] += p * Vs[kk][d];
        }
    }
    float inv = 1.f / lsum;
    float* op = o + ((long)(b * TT + qg) * NHH + h) * HDD;
    #pragma unroll
    for (int d = 0; d < 64; d++) op[d] = acc[d] * inv;
}

// ---------------- tensor-core GEMM (bf16x3 split, fp32-accurate) ----------------
// C(MxN) = [C +] alpha * A(MxK) @ B (or B^T). 128x128x32 block tile, 8 warps,
// warp tile 64x32, mma.sync.m16n8k16 bf16. Each fp32 value is split into
// hi+lo bf16; 3 MMA passes (hh, hl, lh) give ~2^-16 relative accuracy.
// Optional per-batch expert indirection (ti) + scaling (twp), resolved on device.
template<bool ACC, bool TRANSB>
__global__ void __launch_bounds__(256) gemm_kernel(
    const float* __restrict__ A, const float* __restrict__ B, float* __restrict__ C,
    int M, int N, int K,
    const int* __restrict__ ti, const float* __restrict__ twp, int kexp, long estride)
{
    const int bx = blockIdx.x, by = blockIdx.y;
    float alpha = 1.f;
    if (ti) {
        int b = (by * 128) / TT;                 // tile rows never straddle batches
        B += (long)ti[b * 3 + kexp] * estride;
        if (twp) alpha = twp[b * 3 + kexp];
    }

    __shared__ __nv_bfloat16 Ah[128][36];
    __shared__ __nv_bfloat16 Al[128][36];
    __shared__ __nv_bfloat16 Bh[128][36];
    __shared__ __nv_bfloat16 Bl[128][36];

    const int tid  = threadIdx.x;
    const int wid  = tid >> 5, lane = tid & 31;
    const int g    = lane >> 2, t = lane & 3;
    const int m0   = (wid & 1) * 64;          // warp M offset
    const int n0   = (wid >> 1) * 32;         // warp N offset

    // global staging pointers
    const int arow = tid >> 1, acb = (tid & 1) * 16;
    const float* Aptr = A + (long)(by * 128 + arow) * K + acb;
    const float* Bptr;
    if (TRANSB) Bptr = B + (long)(bx * 128 + arow) * K + acb;           // B[N][K]
    else        Bptr = B + (long)(tid >> 3) * N + bx * 128 + (tid & 7) * 16; // B[K][N]

    float4 Areg[4], Breg[4];
    #pragma unroll
    for (int q = 0; q < 4; q++) {
        Areg[q] = *(const float4*)(Aptr + q * 4);
        if (TRANSB) Breg[q] = *(const float4*)(Bptr + q * 4);
        else        Breg[q] = *(const float4*)(Bptr + q * 4);
    }

    float acc[4][4][4];
    #pragma unroll
    for (int i = 0; i < 4; i++)
        #pragma unroll
        for (int j = 0; j < 4; j++)
            #pragma unroll
            for (int e = 0; e < 4; e++) acc[i][j][e] = 0.f;

    for (int k0 = 0; k0 < K; k0 += 32) {
        // ---- convert prefetched regs into hi/lo smem planes ----
        #pragma unroll
        for (int q = 0; q < 4; q++) {
            int c = acb + q * 4;
            unsigned h0, l0, h1, l1;
            split2(Areg[q].x, Areg[q].y, h0, l0);
            split2(Areg[q].z, Areg[q].w, h1, l1);
            *(unsigned*)&Ah[arow][c]     = h0;  *(unsigned*)&Al[arow][c]     = l0;
            *(unsigned*)&Ah[arow][c + 2] = h1;  *(unsigned*)&Al[arow][c + 2] = l1;
        }
        if (TRANSB) {
            #pragma unroll
            for (int q = 0; q < 4; q++) {
                int c = acb + q * 4;
                unsigned h0, l0, h1, l1;
                split2(Breg[q].x, Breg[q].y, h0, l0);
                split2(Breg[q].z, Breg[q].w, h1, l1);
                *(unsigned*)&Bh[arow][c]     = h0;  *(unsigned*)&Bl[arow][c]     = l0;
                *(unsigned*)&Bh[arow][c + 2] = h1;  *(unsigned*)&Bl[arow][c + 2] = l1;
            }
        } else {
            int kr = tid >> 3, nb = (tid & 7) * 16;
            #pragma unroll
            for (int q = 0; q < 4; q++) {
                float f[4] = {Breg[q].x, Breg[q].y, Breg[q].z, Breg[q].w};
                #pragma unroll
                for (int e = 0; e < 4; e++) {
                    int n = nb + q * 4 + e;
                    __nv_bfloat16 h = __float2bfloat16_rn(f[e]);
                    float r = f[e] - __bfloat162float(h);
                    Bh[n][kr] = h;
                    Bl[n][kr] = __float2bfloat16_rn(r);
                }
            }
        }
        __syncthreads();

        // ---- prefetch next k tile ----
        if (k0 + 32 < K) {
            #pragma unroll
            for (int q = 0; q < 4; q++) {
                Areg[q] = *(const float4*)(Aptr + (k0 + 32) + q * 4);
                if (TRANSB) Breg[q] = *(const float4*)(Bptr + (k0 + 32) + q * 4);
                else        Breg[q] = *(const float4*)(Bptr + (long)(k0 + 32) * N + q * 4);
            }
        }

        // ---- compute: 2 x k16 steps ----
        #pragma unroll
        for (int ks = 0; ks < 2; ks++) {
            const int kk = ks * 16;
            unsigned ah[4][4], al[4][4];
            #pragma unroll
            for (int i = 0; i < 4; i++) {
                int r0 = m0 + i * 16 + g, r1 = r0 + 8;
                int c0 = kk + 2 * t, c1 = kk + 8 + 2 * t;
                ah[i][0] = *(const unsigned*)&Ah[r0][c0];
                ah[i][1] = *(const unsigned*)&Ah[r1][c0];
                ah[i][2] = *(const unsigned*)&Ah[r0][c1];
                ah[i][3] = *(const unsigned*)&Ah[r1][c1];
                al[i][0] = *(const unsigned*)&Al[r0][c0];
                al[i][1] = *(const unsigned*)&Al[r1][c0];
                al[i][2] = *(const unsigned*)&Al[r0][c1];
                al[i][3] = *(const unsigned*)&Al[r1][c1];
            }
            #pragma unroll
            for (int j = 0; j < 4; j++) {
                int nr = n0 + j * 8 + g;
                unsigned bh[2], bl[2];
                bh[0] = *(const unsigned*)&Bh[nr][kk + 2 * t];
                bh[1] = *(const unsigned*)&Bh[nr][kk + 8 + 2 * t];
                bl[0] = *(const unsigned*)&Bl[nr][kk + 2 * t];
                bl[1] = *(const unsigned*)&Bl[nr][kk + 8 + 2 * t];
                #pragma unroll
                for (int i = 0; i < 4; i++) {
                    mma16816(acc[i][j], ah[i], bh);
                    mma16816(acc[i][j], ah[i], bl);
                    mma16816(acc[i][j], al[i], bh);
                }
            }
        }
        __syncthreads();
    }

    // ---- epilogue ----
    #pragma unroll
    for (int i = 0; i < 4; i++) {
        long r0 = (long)(by * 128 + m0 + i * 16 + g);
        long r1 = r0 + 8;
        #pragma unroll
        for (int j = 0; j < 4; j++) {
            long c = (long)(bx * 128 + n0 + j * 8 + 2 * t);
            float d0 = acc[i][j][0] * alpha, d1 = acc[i][j][1] * alpha;
            float d2 = acc[i][j][2] * alpha, d3 = acc[i][j][3] * alpha;
            if (ACC) {
                C[r0 * N + c]     += d0;
                C[r0 * N + c + 1] += d1;
                C[r1 * N + c]     += d2;
                C[r1 * N + c + 1] += d3;
            } else {
                *(float2*)&C[r0 * N + c] = make_float2(d0, d1);
                *(float2*)&C[r1 * N + c] = make_float2(d2, d3);
            }
        }
    }
}

// ---------------- launch ----------------
extern "C" void kernel_launch(void* const* d_in, const int* in_sizes, int n_in,
                              void* d_out, int out_size) {
    const int*   idx       = (const int*)  d_in[0];
    const float* cons      = (const float*)d_in[1];
    const float* tok_emb   = (const float*)d_in[2];
    const float* head_g    = (const float*)d_in[3];
    const float* cv_w1     = (const float*)d_in[4];
    const float* cv_b1     = (const float*)d_in[5];
    const float* cv_w2     = (const float*)d_in[6];
    const float* cv_b2     = (const float*)d_in[7];
    const float* tension_w = (const float*)d_in[8];
    const float* ln_attn   = (const float*)d_in[9];
    const float* ln_pf     = (const float*)d_in[10];
    const float* ln_moe    = (const float*)d_in[11];
    const float* ln_f      = (const float*)d_in[12];
    const float* wq        = (const float*)d_in[13];
    const float* wk        = (const float*)d_in[14];
    const float* wv        = (const float*)d_in[15];
    const float* wo        = (const float*)d_in[16];
    const float* pf_gate   = (const float*)d_in[17];
    const float* pf_up     = (const float*)d_in[18];
    const float* pf_down   = (const float*)d_in[19];
    const float* e_gate    = (const float*)d_in[20];
    const float* e_up      = (const float*)d_in[21];
    const float* e_down    = (const float*)d_in[22];
    const float* router_w  = (const float*)d_in[23];
    const float* router_b  = (const float*)d_in[24];
    float* out = (float*)d_out;

    float *xp, *hp, *qp, *kp, *vp, *aop, *b1p, *b2p, *cvp, *twp;
    int* tip;
    cudaGetSymbolAddress((void**)&xp,  g_x);
    cudaGetSymbolAddress((void**)&hp,  g_h);
    cudaGetSymbolAddress((void**)&qp,  g_q);
    cudaGetSymbolAddress((void**)&kp,  g_k);
    cudaGetSymbolAddress((void**)&vp,  g_v);
    cudaGetSymbolAddress((void**)&aop, g_ao);
    cudaGetSymbolAddress((void**)&b1p, g_b1);
    cudaGetSymbolAddress((void**)&b2p, g_b2);
    cudaGetSymbolAddress((void**)&cvp, g_cv);
    cudaGetSymbolAddress((void**)&twp, g_tw);
    cudaGetSymbolAddress((void**)&tip, g_ti);

    float* tens = out + (long)2 * ROWS * VV;   // output tail: tensions (L, B, T)

    embed_kernel<<<(ROWS * DD + 255) / 256, 256>>>(idx, tok_emb, xp);
    cv_kernel<<<1, 256>>>(cons, cv_w1, cv_b1, cv_w2, cv_b2, cvp);

    const dim3 g768 (DD  / 128, ROWS / 128);   // (6, 32)
    const dim3 g256 (256 / 128, ROWS / 128);   // (2, 32)
    const dim3 g1536(DII / 128, ROWS / 128);   // (12, 32)

    for (int l = 0; l < LL; l++) {
        // ---- attention block ----
        rms_kernel<<<ROWS, 256>>>(xp, ln_attn + (long)l * DD, hp);
        gemm_kernel<false, false><<<g768, 256>>>(hp, wq + (long)l * DD * 768, qp,
                                                 ROWS, 768, DD, nullptr, nullptr, 0, 0);
        gemm_kernel<false, false><<<g256, 256>>>(hp, wk + (long)l * DD * 256, kp,
                                                 ROWS, 256, DD, nullptr, nullptr, 0, 0);
        gemm_kernel<false, false><<<g256, 256>>>(hp, wv + (long)l * DD * 256, vp,
                                                 ROWS, 256, DD, nullptr, nullptr, 0, 0);
        attn_kernel<<<dim3(TT / 64, NHH, BB), 64>>>(qp, kp, vp, aop);
        gemm_kernel<true, false><<<g768, 256>>>(aop, wo + (long)l * 768 * DD, xp,
                                                ROWS, DD, 768, nullptr, nullptr, 0, 0);

        // ---- PureField FFN + tension ----
        rms_kernel<<<ROWS, 256>>>(xp, ln_pf + (long)l * DD, hp);
        gemm_kernel<false, false><<<g1536, 256>>>(hp, pf_gate + (long)l * DD * DII, b1p,
                                                  ROWS, DII, DD, nullptr, nullptr, 0, 0);
        gemm_kernel<false, false><<<g1536, 256>>>(hp, pf_up + (long)l * DD * DII, b2p,
                                                  ROWS, DII, DD, nullptr, nullptr, 0, 0);
        swiglu_kernel<<<ROWS, 256>>>(b1p, b2p, b1p, tens + (long)l * ROWS);
        gemm_kernel<true, false><<<g768, 256>>>(b1p, pf_down + (long)l * DII * DD, xp,
                                                ROWS, DD, DII, nullptr, nullptr, 0, 0);

        // ---- consciousness-state residual (previous layer's tension) ----
        if (l > 0)
            csadd_kernel<<<ROWS, 256>>>(xp, tens + (long)(l - 1) * ROWS, tension_w);

        // ---- MoE (top-3 of 10, routed per batch element) ----
        rms_kernel<<<ROWS, 256>>>(xp, ln_moe + (long)l * DD, hp);
        router_kernel<<<1, 32>>>(cvp, router_w + (long)l * 100, router_b + (long)l * 10,
                                 twp, tip);
        for (int kk = 0; kk < 3; kk++) {
            gemm_kernel<false, false><<<g1536, 256>>>(hp, e_gate + (long)l * 10 * DD * DII,
                                                      b1p, ROWS, DII, DD,
                                                      tip, nullptr, kk, (long)DD * DII);
            gemm_kernel<false, false><<<g1536, 256>>>(hp, e_up + (long)l * 10 * DD * DII,
                                                      b2p, ROWS, DII, DD,
                                                      tip, nullptr, kk, (long)DD * DII);
            swiglu_kernel<<<ROWS, 256>>>(b1p, b2p, b1p, nullptr);
            gemm_kernel<true, false><<<g768, 256>>>(b1p, e_down + (long)l * 10 * DII * DD,
                                                    xp, ROWS, DD, DII,
                                                    tip, twp, kk, (long)DII * DD);
        }
    }

    // ---- final norm + tied heads ----
    rms_kernel<<<ROWS, 256>>>(xp, ln_f, hp);
    const dim3 gv(VV / 128, ROWS / 128);       // (250, 32)
    gemm_kernel<false, true><<<gv, 256>>>(hp, tok_emb, out,
                                          ROWS, VV, DD, nullptr, nullptr, 0, 0);
    gemm_kernel<false, true><<<gv, 256>>>(hp, head_g, out + (long)ROWS * VV,
                                          ROWS, VV, DD, nullptr, nullptr, 0, 0);
}

// round 3
// speedup vs baseline: 1.9802x; 1.4490x over previous
#include <cuda_runtime.h>
#include <cuda_bf16.h>
#include <math.h>

// ---------------- dims ----------------
#define BB   2
#define TT   2048
#define DD   768
#define NHH  12
#define NKVV 4
#define HDD  64
#define LL   6
#define VV   32000
#define DII  1536
#define NCC  64
#define CDD  128
#define ROWS (BB*TT)          // 4096
#define GATE_STRENGTH 0.001f

// ---------------- scratch (device globals; no allocation allowed) ----------------
__device__ float g_x [ROWS*DD];
__device__ float g_h [ROWS*DD];
__device__ float g_q [ROWS*NHH*HDD];
__device__ float g_k [ROWS*NKVV*HDD];
__device__ float g_v [ROWS*NKVV*HDD];
__device__ float g_ao[ROWS*NHH*HDD];
__device__ float g_b1[ROWS*DII];
__device__ float g_b2[ROWS*DII];
__device__ float g_cv[BB*10];
__device__ float g_tw[BB*3];
__device__ int   g_ti[BB*3];

// ---------------- helpers ----------------
__device__ __forceinline__ float block_reduce_sum_256(float v) {
    __shared__ float red[8];
    int t = threadIdx.x;
    #pragma unroll
    for (int off = 16; off; off >>= 1) v += __shfl_xor_sync(0xffffffffu, v, off);
    if ((t & 31) == 0) red[t >> 5] = v;
    __syncthreads();
    float tot = 0.f;
    #pragma unroll
    for (int i = 0; i < 8; i++) tot += red[i];
    return tot;
}

__device__ __forceinline__ void split2(float f0, float f1, unsigned& hi, unsigned& lo) {
    __nv_bfloat162 h = __floats2bfloat162_rn(f0, f1);
    float r0 = f0 - __bfloat162float(__low2bfloat16(h));
    float r1 = f1 - __bfloat162float(__high2bfloat16(h));
    __nv_bfloat162 l = __floats2bfloat162_rn(r0, r1);
    hi = *(unsigned*)&h;
    lo = *(unsigned*)&l;
}

__device__ __forceinline__ void mma16816(float* c, const unsigned* a, const unsigned* b) {
    asm volatile(
        "mma.sync.aligned.m16n8k16.row.col.f32.bf16.bf16.f32 "
        "{%0,%1,%2,%3}, {%4,%5,%6,%7}, {%8,%9}, {%0,%1,%2,%3};\n"
        : "+f"(c[0]), "+f"(c[1]), "+f"(c[2]), "+f"(c[3])
        : "r"(a[0]), "r"(a[1]), "r"(a[2]), "r"(a[3]), "r"(b[0]), "r"(b[1]));
}

__device__ __forceinline__ void ldsm_x4(unsigned& r0, unsigned& r1, unsigned& r2,
                                        unsigned& r3, unsigned addr) {
    asm volatile("ldmatrix.sync.aligned.m8n8.x4.shared.b16 {%0,%1,%2,%3}, [%4];\n"
                 : "=r"(r0), "=r"(r1), "=r"(r2), "=r"(r3) : "r"(addr));
}

__device__ __forceinline__ void ldsm_x4_t(unsigned& r0, unsigned& r1, unsigned& r2,
                                          unsigned& r3, unsigned addr) {
    asm volatile("ldmatrix.sync.aligned.m8n8.x4.trans.shared.b16 {%0,%1,%2,%3}, [%4];\n"
                 : "=r"(r0), "=r"(r1), "=r"(r2), "=r"(r3) : "r"(addr));
}

// ---------------- embedding ----------------
__global__ void embed_kernel(const int* __restrict__ idx,
                             const float* __restrict__ emb,
                             float* __restrict__ x) {
    long i = (long)blockIdx.x * blockDim.x + threadIdx.x;
    if (i < (long)ROWS * DD) {
        long r = i / DD, c = i % DD;
        x[i] = emb[(long)idx[r] * DD + c];
    }
}

// ---------------- consciousness vector (tiny MLP) ----------------
__global__ void cv_kernel(const float* __restrict__ cs,
                          const float* __restrict__ w1, const float* __restrict__ b1,
                          const float* __restrict__ w2, const float* __restrict__ b2,
                          float* __restrict__ cv) {
    __shared__ float pooled[BB][CDD];
    __shared__ float h1[BB][64];
    int t = threadIdx.x;  // 256 threads
    {
        int b = t / CDD, c = t % CDD;
        float s = 0.f;
        for (int n = 0; n < NCC; n++)
            s += cs[((long)b * NCC + n) * CDD + c];
        pooled[b][c] = s * (1.f / NCC);
    }
    __syncthreads();
    if (t < BB * 64) {
        int b = t / 64, j = t % 64;
        float z = b1[j];
        for (int c = 0; c < CDD; c++) z += pooled[b][c] * w1[c * 64 + j];
        float z3 = z * z * z;
        h1[b][j] = 0.5f * z * (1.f + tanhf(0.7978845608028654f * (z + 0.044715f * z3)));
    }
    __syncthreads();
    if (t < BB * 10) {
        int b = t / 10, i = t % 10;
        float z = b2[i];
        for (int j = 0; j < 64; j++) z += h1[b][j] * w2[j * 10 + i];
        cv[b * 10 + i] = 1.f / (1.f + expf(-z));
    }
}

// ---------------- RMSNorm ----------------
__global__ void __launch_bounds__(256) rms_kernel(const float* __restrict__ x,
                                                  const float* __restrict__ w,
                                                  float* __restrict__ o) {
    int row = blockIdx.x, t = threadIdx.x;
    const float* xr = x + (long)row * DD;
    float v0 = xr[t], v1 = xr[t + 256], v2 = xr[t + 512];
    float tot = block_reduce_sum_256(v0 * v0 + v1 * v1 + v2 * v2);
    float s = rsqrtf(tot * (1.f / DD) + 1e-6f);
    float* orow = o + (long)row * DD;
    orow[t]       = v0 * s * w[t];
    orow[t + 256] = v1 * s * w[t + 256];
    orow[t + 512] = v2 * s * w[t + 512];
}

// ---------------- SwiGLU (+ optional tension) ----------------
__global__ void __launch_bounds__(256) swiglu_kernel(const float* __restrict__ g,
                                                     const float* __restrict__ u,
                                                     float* __restrict__ hid,
                                                     float* __restrict__ tension) {
    int row = blockIdx.x, t = threadIdx.x;
    const float* gr = g + (long)row * DII;
    const float* ur = u + (long)row * DII;
    float* hr = hid + (long)row * DII;
    float sum = 0.f;
    #pragma unroll
    for (int j = 0; j < 6; j++) {
        int c = t + j * 256;
        float a = gr[c], bv = ur[c];
        float hv = (a / (1.f + __expf(-a))) * bv;
        hr[c] = hv;
        sum += hv;
    }
    if (tension) {
        float tot = block_reduce_sum_256(sum);
        if (t == 0) tension[row] = tanhf(tot * (1.f / DII));
    }
}

// ---------------- consciousness-state residual add ----------------
__global__ void __launch_bounds__(256) csadd_kernel(float* __restrict__ x,
                                                    const float* __restrict__ tension,
                                                    const float* __restrict__ tw) {
    int row = blockIdx.x, t = threadIdx.x;
    float ten = tension[row] * GATE_STRENGTH;
    float* xr = x + (long)row * DD;
    xr[t]       += ten * tw[t];
    xr[t + 256] += ten * tw[t + 256];
    xr[t + 512] += ten * tw[t + 512];
}

// ---------------- router ----------------
__global__ void router_kernel(const float* __restrict__ cv,
                              const float* __restrict__ W,
                              const float* __restrict__ bias,
                              float* __restrict__ tw, int* __restrict__ ti) {
    int b = threadIdx.x;
    if (b >= BB) return;
    float lg[10];
    float mx = -1e30f;
    for (int i = 0; i < 10; i++) {
        float z = bias[i];
        for (int j = 0; j < 10; j++) z += cv[b * 10 + j] * W[j * 10 + i];
        lg[i] = z;
        mx = fmaxf(mx, z);
    }
    float se = 0.f;
    for (int i = 0; i < 10; i++) { lg[i] = expf(lg[i] - mx); se += lg[i]; }
    for (int i = 0; i < 10; i++) lg[i] /= se;
    float wsum = 0.f;
    for (int kk = 0; kk < 3; kk++) {
        int bi = 0; float bv = -1.f;
        for (int i = 0; i < 10; i++) if (lg[i] > bv) { bv = lg[i]; bi = i; }
        ti[b * 3 + kk] = bi; tw[b * 3 + kk] = bv; wsum += bv;
        lg[bi] = -2.f;
    }
    for (int kk = 0; kk < 3; kk++) tw[b * 3 + kk] /= wsum;
}

// ---------------- flash-style causal attention (fp32, GQA) ----------------
__global__ void __launch_bounds__(64) attn_kernel(const float* __restrict__ q,
                                                  const float* __restrict__ k,
                                                  const float* __restrict__ v,
                                                  float* __restrict__ o) {
    const int q0 = blockIdx.x * 64;
    const int h  = blockIdx.y;
    const int b  = blockIdx.z;
    const int t  = threadIdx.x;
    const int qg = q0 + t;
    const int kvh = h / (NHH / NKVV);

    __shared__ float Ks[64][64];
    __shared__ float Vs[64][64];

    float qreg[64], acc[64];
    const float* qp = q + ((long)(b * TT + qg) * NHH + h) * HDD;
    #pragma unroll
    for (int d = 0; d < 64; d++) { qreg[d] = qp[d]; acc[d] = 0.f; }
    float lsum = 0.f;

    for (int s0 = 0; s0 <= q0; s0 += 64) {
        __syncthreads();
        #pragma unroll 8
        for (int r = 0; r < 64; r++) {
            long base = ((long)(b * TT + s0 + r) * NKVV + kvh) * HDD + t;
            Ks[r][t] = k[base];
            Vs[r][t] = v[base];
        }
        __syncthreads();
        int kmax = min(64, qg - s0 + 1);
        for (int kk = 0; kk < kmax; kk++) {
            float s = 0.f;
            #pragma unroll
            for (int d = 0; d < 64; d++) s += qreg[d] * Ks[kk][d];
            float p = __expf(s * 0.125f);
            lsum += p;
            #pragma unroll
            for (int d = 0; d < 64; d++) acc[d] += p * Vs[kk][d];
        }
    }
    float inv = 1.f / lsum;
    float* op = o + ((long)(b * TT + qg) * NHH + h) * HDD;
    #pragma unroll
    for (int d = 0; d < 64; d++) op[d] = acc[d] * inv;
}

// ---------------- tensor-core GEMM (bf16x3 split + ldmatrix) ----------------
// C(MxN) = [C +] alpha * A(MxK) @ B (or B^T). 128x128x32 block tile, 8 warps,
// warp tile 64x32. Fragment loads via ldmatrix.x4 (conflict-free padded smem).
// Optional second (B2,C2) problem selected by blockIdx.z (same M,N,K).
// Optional per-batch expert indirection (ti) + scaling (twp).
template<bool ACC, bool TRANSB>
__global__ void __launch_bounds__(256) gemm_kernel(
    const float* __restrict__ A, const float* __restrict__ B, float* __restrict__ C,
    const float* __restrict__ B2, float* __restrict__ C2,
    int M, int N, int K,
    const int* __restrict__ ti, const float* __restrict__ twp, int kexp, long estride)
{
    const int bx = blockIdx.x, by = blockIdx.y;
    if (B2 != nullptr && blockIdx.z == 1) { B = B2; C = C2; }
    float alpha = 1.f;
    if (ti) {
        int b = (by * 128) / TT;                 // tile rows never straddle batches
        B += (long)ti[b * 3 + kexp] * estride;
        if (twp) alpha = twp[b * 3 + kexp];
    }

    // A planes: [128][40] halfs (pad -> conflict-free ldmatrix)
    __shared__ __nv_bfloat16 Ah[128 * 40];
    __shared__ __nv_bfloat16 Al[128 * 40];
    // B planes: TRANSB -> [n][k] = [128][40] ; else -> [k][n] = [32][136]
    constexpr int BELEMS = TRANSB ? 128 * 40 : 32 * 136;
    __shared__ __nv_bfloat16 Bh[BELEMS];
    __shared__ __nv_bfloat16 Bl[BELEMS];

    const int tid  = threadIdx.x;
    const int wid  = tid >> 5, lane = tid & 31;
    const int g    = lane >> 2, t = lane & 3;
    const int m0   = (wid & 1) * 64;          // warp M offset
    const int n0   = (wid >> 1) * 32;         // warp N offset

    const unsigned sAh = (unsigned)__cvta_generic_to_shared(Ah);
    const unsigned sAl = (unsigned)__cvta_generic_to_shared(Al);
    const unsigned sBh = (unsigned)__cvta_generic_to_shared(Bh);
    const unsigned sBl = (unsigned)__cvta_generic_to_shared(Bl);

    // global staging
    const int arow = tid >> 1, acb = (tid & 1) * 16;
    const float* Aptr = A + (long)(by * 128 + arow) * K + acb;
    const float* Bptr;
    if (TRANSB) Bptr = B + (long)(bx * 128 + arow) * K + acb;                 // B[N][K]
    else        Bptr = B + (long)(tid >> 3) * N + bx * 128 + (tid & 7) * 16;  // B[K][N]

    float4 Areg[4], Breg[4];
    #pragma unroll
    for (int q = 0; q < 4; q++) {
        Areg[q] = *(const float4*)(Aptr + q * 4);
        Breg[q] = *(const float4*)(Bptr + q * 4);
    }

    float acc[4][4][4];
    #pragma unroll
    for (int i = 0; i < 4; i++)
        #pragma unroll
        for (int j = 0; j < 4; j++)
            #pragma unroll
            for (int e = 0; e < 4; e++) acc[i][j][e] = 0.f;

    for (int k0 = 0; k0 < K; k0 += 32) {
        // ---- convert prefetched regs into hi/lo smem planes (vectorized) ----
        #pragma unroll
        for (int q = 0; q < 4; q++) {
            int c = acb + q * 4;
            unsigned h0, l0, h1, l1;
            split2(Areg[q].x, Areg[q].y, h0, l0);
            split2(Areg[q].z, Areg[q].w, h1, l1);
            *(uint2*)&Ah[arow * 40 + c] = make_uint2(h0, h1);
            *(uint2*)&Al[arow * 40 + c] = make_uint2(l0, l1);
        }
        if (TRANSB) {
            #pragma unroll
            for (int q = 0; q < 4; q++) {
                int c = acb + q * 4;
                unsigned h0, l0, h1, l1;
                split2(Breg[q].x, Breg[q].y, h0, l0);
                split2(Breg[q].z, Breg[q].w, h1, l1);
                *(uint2*)&Bh[arow * 40 + c] = make_uint2(h0, h1);
                *(uint2*)&Bl[arow * 40 + c] = make_uint2(l0, l1);
            }
        } else {
            const int kr = tid >> 3, nb = (tid & 7) * 16;
            #pragma unroll
            for (int q = 0; q < 4; q++) {
                int c = nb + q * 4;
                unsigned h0, l0, h1, l1;
                split2(Breg[q].x, Breg[q].y, h0, l0);
                split2(Breg[q].z, Breg[q].w, h1, l1);
                *(uint2*)&Bh[kr * 136 + c] = make_uint2(h0, h1);
                *(uint2*)&Bl[kr * 136 + c] = make_uint2(l0, l1);
            }
        }
        __syncthreads();

        // ---- prefetch next k tile ----
        if (k0 + 32 < K) {
            #pragma unroll
            for (int q = 0; q < 4; q++) {
                Areg[q] = *(const float4*)(Aptr + (k0 + 32) + q * 4);
                if (TRANSB) Breg[q] = *(const float4*)(Bptr + (k0 + 32) + q * 4);
                else        Breg[q] = *(const float4*)(Bptr + (long)(k0 + 32) * N + q * 4);
            }
        }

        // ---- compute: 2 x k16 steps ----
        #pragma unroll
        for (int ks = 0; ks < 2; ks++) {
            const int kk = ks * 16;
            unsigned ah[4][4], al[4][4];
            #pragma unroll
            for (int i = 0; i < 4; i++) {
                int row = m0 + i * 16 + (lane & 15);
                int col = kk + (lane >> 4) * 8;
                unsigned off = (unsigned)(row * 40 + col) * 2u;
                ldsm_x4(ah[i][0], ah[i][1], ah[i][2], ah[i][3], sAh + off);
                ldsm_x4(al[i][0], al[i][1], al[i][2], al[i][3], sAl + off);
            }
            unsigned bh[4][2], bl[4][2];
            if (TRANSB) {
                #pragma unroll
                for (int jp = 0; jp < 2; jp++) {
                    int row = n0 + jp * 16 + (lane & 15);
                    int col = kk + (lane >> 4) * 8;
                    unsigned off = (unsigned)(row * 40 + col) * 2u;
                    unsigned r0, r1, r2, r3;
                    ldsm_x4(r0, r1, r2, r3, sBh + off);
                    bh[2*jp][0] = r0; bh[2*jp+1][0] = r1;
                    bh[2*jp][1] = r2; bh[2*jp+1][1] = r3;
                    ldsm_x4(r0, r1, r2, r3, sBl + off);
                    bl[2*jp][0] = r0; bl[2*jp+1][0] = r1;
                    bl[2*jp][1] = r2; bl[2*jp+1][1] = r3;
                }
            } else {
                #pragma unroll
                for (int jp = 0; jp < 2; jp++) {
                    int row = kk + (lane & 15);
                    int col = n0 + jp * 16 + (lane >> 4) * 8;
                    unsigned off = (unsigned)(row * 136 + col) * 2u;
                    unsigned r0, r1, r2, r3;
                    ldsm_x4_t(r0, r1, r2, r3, sBh + off);
                    bh[2*jp][0] = r0; bh[2*jp][1] = r1;
                    bh[2*jp+1][0] = r2; bh[2*jp+1][1] = r3;
                    ldsm_x4_t(r0, r1, r2, r3, sBl + off);
                    bl[2*jp][0] = r0; bl[2*jp][1] = r1;
                    bl[2*jp+1][0] = r2; bl[2*jp+1][1] = r3;
                }
            }
            #pragma unroll
            for (int j = 0; j < 4; j++) {
                #pragma unroll
                for (int i = 0; i < 4; i++) {
                    mma16816(acc[i][j], ah[i], bh[j]);
                    mma16816(acc[i][j], ah[i], bl[j]);
                    mma16816(acc[i][j], al[i], bh[j]);
                }
            }
        }
        __syncthreads();
    }

    // ---- epilogue ----
    #pragma unroll
    for (int i = 0; i < 4; i++) {
        long r0 = (long)(by * 128 + m0 + i * 16 + g);
        long r1 = r0 + 8;
        #pragma unroll
        for (int j = 0; j < 4; j++) {
            long c = (long)(bx * 128 + n0 + j * 8 + 2 * t);
            float d0 = acc[i][j][0] * alpha, d1 = acc[i][j][1] * alpha;
            float d2 = acc[i][j][2] * alpha, d3 = acc[i][j][3] * alpha;
            if (ACC) {
                C[r0 * N + c]     += d0;
                C[r0 * N + c + 1] += d1;
                C[r1 * N + c]     += d2;
                C[r1 * N + c + 1] += d3;
            } else {
                *(float2*)&C[r0 * N + c] = make_float2(d0, d1);
                *(float2*)&C[r1 * N + c] = make_float2(d2, d3);
            }
        }
    }
}

// ---------------- launch ----------------
extern "C" void kernel_launch(void* const* d_in, const int* in_sizes, int n_in,
                              void* d_out, int out_size) {
    const int*   idx       = (const int*)  d_in[0];
    const float* cons      = (const float*)d_in[1];
    const float* tok_emb   = (const float*)d_in[2];
    const float* head_g    = (const float*)d_in[3];
    const float* cv_w1     = (const float*)d_in[4];
    const float* cv_b1     = (const float*)d_in[5];
    const float* cv_w2     = (const float*)d_in[6];
    const float* cv_b2     = (const float*)d_in[7];
    const float* tension_w = (const float*)d_in[8];
    const float* ln_attn   = (const float*)d_in[9];
    const float* ln_pf     = (const float*)d_in[10];
    const float* ln_moe    = (const float*)d_in[11];
    const float* ln_f      = (const float*)d_in[12];
    const float* wq        = (const float*)d_in[13];
    const float* wk        = (const float*)d_in[14];
    const float* wv        = (const float*)d_in[15];
    const float* wo        = (const float*)d_in[16];
    const float* pf_gate   = (const float*)d_in[17];
    const float* pf_up     = (const float*)d_in[18];
    const float* pf_down   = (const float*)d_in[19];
    const float* e_gate    = (const float*)d_in[20];
    const float* e_up      = (const float*)d_in[21];
    const float* e_down    = (const float*)d_in[22];
    const float* router_w  = (const float*)d_in[23];
    const float* router_b  = (const float*)d_in[24];
    float* out = (float*)d_out;

    float *xp, *hp, *qp, *kp, *vp, *aop, *b1p, *b2p, *cvp, *twp;
    int* tip;
    cudaGetSymbolAddress((void**)&xp,  g_x);
    cudaGetSymbolAddress((void**)&hp,  g_h);
    cudaGetSymbolAddress((void**)&qp,  g_q);
    cudaGetSymbolAddress((void**)&kp,  g_k);
    cudaGetSymbolAddress((void**)&vp,  g_v);
    cudaGetSymbolAddress((void**)&aop, g_ao);
    cudaGetSymbolAddress((void**)&b1p, g_b1);
    cudaGetSymbolAddress((void**)&b2p, g_b2);
    cudaGetSymbolAddress((void**)&cvp, g_cv);
    cudaGetSymbolAddress((void**)&twp, g_tw);
    cudaGetSymbolAddress((void**)&tip, g_ti);

    float* tens = out + (long)2 * ROWS * VV;   // output tail: tensions (L, B, T)

    embed_kernel<<<(ROWS * DD + 255) / 256, 256>>>(idx, tok_emb, xp);
    cv_kernel<<<1, 256>>>(cons, cv_w1, cv_b1, cv_w2, cv_b2, cvp);

    const dim3 g768 (DD  / 128, ROWS / 128, 1);   // (6, 32)
    const dim3 gkv  (256 / 128, ROWS / 128, 2);   // paired K & V
    const dim3 gff  (DII / 128, ROWS / 128, 2);   // paired gate & up

    for (int l = 0; l < LL; l++) {
        // ---- attention block ----
        rms_kernel<<<ROWS, 256>>>(xp, ln_attn + (long)l * DD, hp);
        gemm_kernel<false, false><<<g768, 256>>>(hp, wq + (long)l * DD * 768, qp,
                                                 nullptr, nullptr,
                                                 ROWS, 768, DD, nullptr, nullptr, 0, 0);
        gemm_kernel<false, false><<<gkv, 256>>>(hp, wk + (long)l * DD * 256, kp,
                                                wv + (long)l * DD * 256, vp,
                                                ROWS, 256, DD, nullptr, nullptr, 0, 0);
        attn_kernel<<<dim3(TT / 64, NHH, BB), 64>>>(qp, kp, vp, aop);
        gemm_kernel<true, false><<<g768, 256>>>(aop, wo + (long)l * 768 * DD, xp,
                                                nullptr, nullptr,
                                                ROWS, DD, 768, nullptr, nullptr, 0, 0);

        // ---- PureField FFN + tension ----
        rms_kernel<<<ROWS, 256>>>(xp, ln_pf + (long)l * DD, hp);
        gemm_kernel<false, false><<<gff, 256>>>(hp, pf_gate + (long)l * DD * DII, b1p,
                                                pf_up + (long)l * DD * DII, b2p,
                                                ROWS, DII, DD, nullptr, nullptr, 0, 0);
        swiglu_kernel<<<ROWS, 256>>>(b1p, b2p, b1p, tens + (long)l * ROWS);
        gemm_kernel<true, false><<<g768, 256>>>(b1p, pf_down + (long)l * DII * DD, xp,
                                                nullptr, nullptr,
                                                ROWS, DD, DII, nullptr, nullptr, 0, 0);

        // ---- consciousness-state residual (previous layer's tension) ----
        if (l > 0)
            csadd_kernel<<<ROWS, 256>>>(xp, tens + (long)(l - 1) * ROWS, tension_w);

        // ---- MoE (top-3 of 10, routed per batch element) ----
        rms_kernel<<<ROWS, 256>>>(xp, ln_moe + (long)l * DD, hp);
        router_kernel<<<1, 32>>>(cvp, router_w + (long)l * 100, router_b + (long)l * 10,
                                 twp, tip);
        for (int kk = 0; kk < 3; kk++) {
            gemm_kernel<false, false><<<gff, 256>>>(hp, e_gate + (long)l * 10 * DD * DII,
                                                    b1p, e_up + (long)l * 10 * DD * DII,
                                                    b2p, ROWS, DII, DD,
                                                    tip, nullptr, kk, (long)DD * DII);
            swiglu_kernel<<<ROWS, 256>>>(b1p, b2p, b1p, nullptr);
            gemm_kernel<true, false><<<g768, 256>>>(b1p, e_down + (long)l * 10 * DII * DD,
                                                    xp, nullptr, nullptr,
                                                    ROWS, DD, DII,
                                                    tip, twp, kk, (long)DII * DD);
        }
    }

    // ---- final norm + tied heads (paired) ----
    rms_kernel<<<ROWS, 256>>>(xp, ln_f, hp);
    const dim3 gv(VV / 128, ROWS / 128, 2);       // (250, 32, 2)
    gemm_kernel<false, true><<<gv, 256>>>(hp, tok_emb, out,
                                          head_g, out + (long)ROWS * VV,
                                          ROWS, VV, DD, nullptr, nullptr, 0, 0);
}

// round 4
// speedup vs baseline: 2.0284x; 1.0243x over previous
#include <cuda_runtime.h>
#include <cuda_bf16.h>
#include <math.h>

// ---------------- dims ----------------
#define BB   2
#define TT   2048
#define DD   768
#define NHH  12
#define NKVV 4
#define HDD  64
#define LL   6
#define VV   32000
#define DII  1536
#define NCC  64
#define CDD  128
#define ROWS (BB*TT)          // 4096
#define GATE_STRENGTH 0.001f

// ---------------- scratch (device globals; no allocation allowed) ----------------
__device__ float g_x [ROWS*DD];
__device__ float g_h [ROWS*DD];
__device__ float g_q [ROWS*NHH*HDD];
__device__ float g_k [ROWS*NKVV*HDD];
__device__ float g_v [ROWS*NKVV*HDD];
__device__ float g_ao[ROWS*NHH*HDD];
__device__ float g_eb[6L*ROWS*DII];   // 6 expert/pf hidden buffers
__device__ float g_cv[BB*10];
__device__ float g_tw[BB*3];
__device__ int   g_ti[BB*3];

// ---------------- helpers ----------------
__device__ __forceinline__ float block_reduce_sum_256(float v) {
    __shared__ float red[8];
    int t = threadIdx.x;
    #pragma unroll
    for (int off = 16; off; off >>= 1) v += __shfl_xor_sync(0xffffffffu, v, off);
    if ((t & 31) == 0) red[t >> 5] = v;
    __syncthreads();
    float tot = 0.f;
    #pragma unroll
    for (int i = 0; i < 8; i++) tot += red[i];
    return tot;
}

__device__ __forceinline__ void split2(float f0, float f1, unsigned& hi, unsigned& lo) {
    __nv_bfloat162 h = __floats2bfloat162_rn(f0, f1);
    float r0 = f0 - __bfloat162float(__low2bfloat16(h));
    float r1 = f1 - __bfloat162float(__high2bfloat16(h));
    __nv_bfloat162 l = __floats2bfloat162_rn(r0, r1);
    hi = *(unsigned*)&h;
    lo = *(unsigned*)&l;
}

__device__ __forceinline__ void mma16816(float* c, const unsigned* a, const unsigned* b) {
    asm volatile(
        "mma.sync.aligned.m16n8k16.row.col.f32.bf16.bf16.f32 "
        "{%0,%1,%2,%3}, {%4,%5,%6,%7}, {%8,%9}, {%0,%1,%2,%3};\n"
        : "+f"(c[0]), "+f"(c[1]), "+f"(c[2]), "+f"(c[3])
        : "r"(a[0]), "r"(a[1]), "r"(a[2]), "r"(a[3]), "r"(b[0]), "r"(b[1]));
}

__device__ __forceinline__ void ldsm_x4(unsigned& r0, unsigned& r1, unsigned& r2,
                                        unsigned& r3, unsigned addr) {
    asm volatile("ldmatrix.sync.aligned.m8n8.x4.shared.b16 {%0,%1,%2,%3}, [%4];\n"
                 : "=r"(r0), "=r"(r1), "=r"(r2), "=r"(r3) : "r"(addr));
}

__device__ __forceinline__ void ldsm_x4_t(unsigned& r0, unsigned& r1, unsigned& r2,
                                          unsigned& r3, unsigned addr) {
    asm volatile("ldmatrix.sync.aligned.m8n8.x4.trans.shared.b16 {%0,%1,%2,%3}, [%4];\n"
                 : "=r"(r0), "=r"(r1), "=r"(r2), "=r"(r3) : "r"(addr));
}

// ---------------- embedding ----------------
__global__ void embed_kernel(const int* __restrict__ idx,
                             const float* __restrict__ emb,
                             float* __restrict__ x) {
    long i = (long)blockIdx.x * blockDim.x + threadIdx.x;
    if (i < (long)ROWS * DD) {
        long r = i / DD, c = i % DD;
        x[i] = emb[(long)idx[r] * DD + c];
    }
}

// ---------------- consciousness vector (tiny MLP) ----------------
__global__ void cv_kernel(const float* __restrict__ cs,
                          const float* __restrict__ w1, const float* __restrict__ b1,
                          const float* __restrict__ w2, const float* __restrict__ b2,
                          float* __restrict__ cv) {
    __shared__ float pooled[BB][CDD];
    __shared__ float h1[BB][64];
    int t = threadIdx.x;  // 256 threads
    {
        int b = t / CDD, c = t % CDD;
        float s = 0.f;
        for (int n = 0; n < NCC; n++)
            s += cs[((long)b * NCC + n) * CDD + c];
        pooled[b][c] = s * (1.f / NCC);
    }
    __syncthreads();
    if (t < BB * 64) {
        int b = t / 64, j = t % 64;
        float z = b1[j];
        for (int c = 0; c < CDD; c++) z += pooled[b][c] * w1[c * 64 + j];
        float z3 = z * z * z;
        h1[b][j] = 0.5f * z * (1.f + tanhf(0.7978845608028654f * (z + 0.044715f * z3)));
    }
    __syncthreads();
    if (t < BB * 10) {
        int b = t / 10, i = t % 10;
        float z = b2[i];
        for (int j = 0; j < 64; j++) z += h1[b][j] * w2[j * 10 + i];
        cv[b * 10 + i] = 1.f / (1.f + expf(-z));
    }
}

// ---------------- RMSNorm ----------------
__global__ void __launch_bounds__(256) rms_kernel(const float* __restrict__ x,
                                                  const float* __restrict__ w,
                                                  float* __restrict__ o) {
    int row = blockIdx.x, t = threadIdx.x;
    const float* xr = x + (long)row * DD;
    float v0 = xr[t], v1 = xr[t + 256], v2 = xr[t + 512];
    float tot = block_reduce_sum_256(v0 * v0 + v1 * v1 + v2 * v2);
    float s = rsqrtf(tot * (1.f / DD) + 1e-6f);
    float* orow = o + (long)row * DD;
    orow[t]       = v0 * s * w[t];
    orow[t + 256] = v1 * s * w[t + 256];
    orow[t + 512] = v2 * s * w[t + 512];
}

// ---------------- SwiGLU (+ optional tension) — PureField ----------------
__global__ void __launch_bounds__(256) swiglu_kernel(const float* __restrict__ g,
                                                     const float* __restrict__ u,
                                                     float* __restrict__ hid,
                                                     float* __restrict__ tension) {
    int row = blockIdx.x, t = threadIdx.x;
    const float* gr = g + (long)row * DII;
    const float* ur = u + (long)row * DII;
    float* hr = hid + (long)row * DII;
    float sum = 0.f;
    #pragma unroll
    for (int j = 0; j < 6; j++) {
        int c = t + j * 256;
        float a = gr[c], bv = ur[c];
        float hv = (a / (1.f + __expf(-a))) * bv;
        hr[c] = hv;
        sum += hv;
    }
    if (tension) {
        float tot = block_reduce_sum_256(sum);
        if (t == 0) tension[row] = tanhf(tot * (1.f / DII));
    }
}

// ---------------- SwiGLU for MoE: 3 experts, folds router weight in ----------------
__global__ void __launch_bounds__(256) swiglu_moe_kernel(float* __restrict__ buf,
                                                         const float* __restrict__ tw) {
    int row = blockIdx.x, e = blockIdx.y, t = threadIdx.x;
    int b = row / TT;
    float scale = tw[b * 3 + e];
    const float* gr = buf + (long)(2 * e) * ROWS * DII + (long)row * DII;
    const float* ur = buf + (long)(2 * e + 1) * ROWS * DII + (long)row * DII;
    float* hr = (float*)gr;   // in-place into gate buffer
    #pragma unroll
    for (int j = 0; j < 6; j++) {
        int c = t + j * 256;
        float a = gr[c], bv = ur[c];
        hr[c] = (a / (1.f + __expf(-a))) * bv * scale;
    }
}

// ---------------- consciousness-state residual add ----------------
__global__ void __launch_bounds__(256) csadd_kernel(float* __restrict__ x,
                                                    const float* __restrict__ tension,
                                                    const float* __restrict__ tw) {
    int row = blockIdx.x, t = threadIdx.x;
    float ten = tension[row] * GATE_STRENGTH;
    float* xr = x + (long)row * DD;
    xr[t]       += ten * tw[t];
    xr[t + 256] += ten * tw[t + 256];
    xr[t + 512] += ten * tw[t + 512];
}

// ---------------- router ----------------
__global__ void router_kernel(const float* __restrict__ cv,
                              const float* __restrict__ W,
                              const float* __restrict__ bias,
                              float* __restrict__ tw, int* __restrict__ ti) {
    int b = threadIdx.x;
    if (b >= BB) return;
    float lg[10];
    float mx = -1e30f;
    for (int i = 0; i < 10; i++) {
        float z = bias[i];
        for (int j = 0; j < 10; j++) z += cv[b * 10 + j] * W[j * 10 + i];
        lg[i] = z;
        mx = fmaxf(mx, z);
    }
    float se = 0.f;
    for (int i = 0; i < 10; i++) { lg[i] = expf(lg[i] - mx); se += lg[i]; }
    for (int i = 0; i < 10; i++) lg[i] /= se;
    float wsum = 0.f;
    for (int kk = 0; kk < 3; kk++) {
        int bi = 0; float bv = -1.f;
        for (int i = 0; i < 10; i++) if (lg[i] > bv) { bv = lg[i]; bi = i; }
        ti[b * 3 + kk] = bi; tw[b * 3 + kk] = bv; wsum += bv;
        lg[bi] = -2.f;
    }
    for (int kk = 0; kk < 3; kk++) tw[b * 3 + kk] /= wsum;
}

// ---------------- flash-style causal attention (fp32, GQA) ----------------
__global__ void __launch_bounds__(64) attn_kernel(const float* __restrict__ q,
                                                  const float* __restrict__ k,
                                                  const float* __restrict__ v,
                                                  float* __restrict__ o) {
    const int q0 = blockIdx.x * 64;
    const int h  = blockIdx.y;
    const int b  = blockIdx.z;
    const int t  = threadIdx.x;
    const int qg = q0 + t;
    const int kvh = h / (NHH / NKVV);

    __shared__ float Ks[64][64];
    __shared__ float Vs[64][64];

    float qreg[64], acc[64];
    const float* qp = q + ((long)(b * TT + qg) * NHH + h) * HDD;
    #pragma unroll
    for (int d = 0; d < 64; d++) { qreg[d] = qp[d]; acc[d] = 0.f; }
    float lsum = 0.f;

    for (int s0 = 0; s0 <= q0; s0 += 64) {
        __syncthreads();
        #pragma unroll 8
        for (int r = 0; r < 64; r++) {
            long base = ((long)(b * TT + s0 + r) * NKVV + kvh) * HDD + t;
            Ks[r][t] = k[base];
            Vs[r][t] = v[base];
        }
        __syncthreads();
        int kmax = min(64, qg - s0 + 1);
        for (int kk = 0; kk < kmax; kk++) {
            float s = 0.f;
            #pragma unroll
            for (int d = 0; d < 64; d++) s += qreg[d] * Ks[kk][d];
            float p = __expf(s * 0.125f);
            lsum += p;
            #pragma unroll
            for (int d = 0; d < 64; d++) acc[d] += p * Vs[kk][d];
        }
    }
    float inv = 1.f / lsum;
    float* op = o + ((long)(b * TT + qg) * NHH + h) * HDD;
    #pragma unroll
    for (int d = 0; d < 64; d++) op[d] = acc[d] * inv;
}

// ---------------- tensor-core GEMM (bf16x3 + ldmatrix + 2-stage pipeline) ----------
// MODE 0: C(MxN) = [C +] A @ B(/B^T); optional 2nd problem (B2,C2) via blockIdx.z.
// MODE 1: MoE gate/up: z in [0,6): kexp=z>>1, which=z&1; B = (which?B2:B) +
//         ti[b*3+kexp]*estride; C = C + z*ROWS*N.   (non-trans B only)
// MODE 2: MoE down: 3 K-segments; A segment s at A + 2*s*ROWS*K; B segment s at
//         B + ti[b*3+s]*estride. ACC epilogue. (expert weight pre-folded into A)
#define ASZ (128*40)
template<bool TRANSB> __host__ __device__ constexpr int bsz() { return TRANSB ? 128*40 : 32*136; }
template<bool TRANSB> __host__ __device__ constexpr int smem_bytes() {
    return (4 * ASZ + 4 * bsz<TRANSB>()) * 2;
}

template<bool ACC, bool TRANSB, int MODE>
__global__ void __launch_bounds__(256) gemm_kernel(
    const float* __restrict__ A, const float* __restrict__ B, float* __restrict__ C,
    const float* __restrict__ B2, float* __restrict__ C2,
    int M, int N, int K,
    const int* __restrict__ ti, long estride)
{
    const int bx = blockIdx.x, by = blockIdx.y;
    const int b3 = ((by * 128) / TT) * 3;     // batch*3 (tiles never straddle batches)
    if (MODE == 0) {
        if (B2 != nullptr && blockIdx.z == 1) { B = B2; C = C2; }
    } else if (MODE == 1) {
        const int z = blockIdx.z, kexp = z >> 1;
        B = ((z & 1) ? B2 : B) + (long)ti[b3 + kexp] * estride;
        C = C + (long)z * ROWS * N;
    }
    int tseg[3];
    if (MODE == 2) {
        tseg[0] = ti[b3]; tseg[1] = ti[b3 + 1]; tseg[2] = ti[b3 + 2];
    }

    extern __shared__ char smem_raw[];
    constexpr int BSZ = bsz<TRANSB>();
    __nv_bfloat16* Ah = (__nv_bfloat16*)smem_raw;       // [2][ASZ]
    __nv_bfloat16* Al = Ah + 2 * ASZ;
    __nv_bfloat16* Bh = Al + 2 * ASZ;                   // [2][BSZ]
    __nv_bfloat16* Bl = Bh + 2 * BSZ;

    const int tid  = threadIdx.x;
    const int wid  = tid >> 5, lane = tid & 31;
    const int g    = lane >> 2, t = lane & 3;
    const int m0   = (wid & 1) * 64;
    const int n0   = (wid >> 1) * 32;

    const unsigned sAh = (unsigned)__cvta_generic_to_shared(Ah);
    const unsigned sAl = (unsigned)__cvta_generic_to_shared(Al);
    const unsigned sBh = (unsigned)__cvta_generic_to_shared(Bh);
    const unsigned sBl = (unsigned)__cvta_generic_to_shared(Bl);

    const int arow = tid >> 1, acb = (tid & 1) * 16;
    const int kIters = K >> 5;
    const int total  = (MODE == 2 ? 3 : 1) * kIters;

    float4 Areg[4], Breg[4];

    auto prefetch = [&](int it) {
        int seg = (MODE == 2) ? it / kIters : 0;
        int k0  = (MODE == 2) ? (it % kIters) * 32 : it * 32;
        const float* Ap = A + ((MODE == 2) ? (long)2 * seg * ROWS * K : 0)
                            + (long)(by * 128 + arow) * K + k0 + acb;
        #pragma unroll
        for (int q = 0; q < 4; q++) Areg[q] = *(const float4*)(Ap + q * 4);
        if (TRANSB) {
            const float* Bp = B + (long)(bx * 128 + arow) * K + k0 + acb;
            #pragma unroll
            for (int q = 0; q < 4; q++) Breg[q] = *(const float4*)(Bp + q * 4);
        } else {
            const float* Bb = (MODE == 2) ? B + (long)tseg[seg] * estride : B;
            const float* Bp = Bb + (long)(k0 + (tid >> 3)) * N + bx * 128 + (tid & 7) * 16;
            #pragma unroll
            for (int q = 0; q < 4; q++) Breg[q] = *(const float4*)(Bp + q * 4);
        }
    };

    auto store_stage = [&](int st) {
        __nv_bfloat16* ah = Ah + st * ASZ;
        __nv_bfloat16* al = Al + st * ASZ;
        __nv_bfloat16* bh = Bh + st * BSZ;
        __nv_bfloat16* bl = Bl + st * BSZ;
        #pragma unroll
        for (int q = 0; q < 4; q++) {
            int c = acb + q * 4;
            unsigned h0, l0, h1, l1;
            split2(Areg[q].x, Areg[q].y, h0, l0);
            split2(Areg[q].z, Areg[q].w, h1, l1);
            *(uint2*)&ah[arow * 40 + c] = make_uint2(h0, h1);
            *(uint2*)&al[arow * 40 + c] = make_uint2(l0, l1);
        }
        if (TRANSB) {
            #pragma unroll
            for (int q = 0; q < 4; q++) {
                int c = acb + q * 4;
                unsigned h0, l0, h1, l1;
                split2(Breg[q].x, Breg[q].y, h0, l0);
                split2(Breg[q].z, Breg[q].w, h1, l1);
                *(uint2*)&bh[arow * 40 + c] = make_uint2(h0, h1);
                *(uint2*)&bl[arow * 40 + c] = make_uint2(l0, l1);
            }
        } else {
            const int kr = tid >> 3, nb = (tid & 7) * 16;
            #pragma unroll
            for (int q = 0; q < 4; q++) {
                int c = nb + q * 4;
                unsigned h0, l0, h1, l1;
                split2(Breg[q].x, Breg[q].y, h0, l0);
                split2(Breg[q].z, Breg[q].w, h1, l1);
                *(uint2*)&bh[kr * 136 + c] = make_uint2(h0, h1);
                *(uint2*)&bl[kr * 136 + c] = make_uint2(l0, l1);
            }
        }
    };

    float acc[4][4][4];
    #pragma unroll
    for (int i = 0; i < 4; i++)
        #pragma unroll
        for (int j = 0; j < 4; j++)
            #pragma unroll
            for (int e = 0; e < 4; e++) acc[i][j][e] = 0.f;

    prefetch(0);
    store_stage(0);
    __syncthreads();

    for (int it = 0; it < total; it++) {
        const int st = it & 1;
        if (it + 1 < total) prefetch(it + 1);

        // ---- compute on stage st ----
        const unsigned aOff = (unsigned)(st * ASZ) * 2u;
        const unsigned bOff = (unsigned)(st * BSZ) * 2u;
        #pragma unroll
        for (int ks = 0; ks < 2; ks++) {
            const int kk = ks * 16;
            unsigned ah[4][4], al[4][4];
            #pragma unroll
            for (int i = 0; i < 4; i++) {
                int row = m0 + i * 16 + (lane & 15);
                int col = kk + (lane >> 4) * 8;
                unsigned off = (unsigned)(row * 40 + col) * 2u;
                ldsm_x4(ah[i][0], ah[i][1], ah[i][2], ah[i][3], sAh + aOff + off);
                ldsm_x4(al[i][0], al[i][1], al[i][2], al[i][3], sAl + aOff + off);
            }
            unsigned bh[4][2], bl[4][2];
            if (TRANSB) {
                #pragma unroll
                for (int jp = 0; jp < 2; jp++) {
                    int row = n0 + jp * 16 + (lane & 15);
                    int col = kk + (lane >> 4) * 8;
                    unsigned off = (unsigned)(row * 40 + col) * 2u;
                    unsigned r0, r1, r2, r3;
                    ldsm_x4(r0, r1, r2, r3, sBh + bOff + off);
                    bh[2*jp][0] = r0; bh[2*jp+1][0] = r1;
                    bh[2*jp][1] = r2; bh[2*jp+1][1] = r3;
                    ldsm_x4(r0, r1, r2, r3, sBl + bOff + off);
                    bl[2*jp][0] = r0; bl[2*jp+1][0] = r1;
                    bl[2*jp][1] = r2; bl[2*jp+1][1] = r3;
                }
            } else {
                #pragma unroll
                for (int jp = 0; jp < 2; jp++) {
                    int row = kk + (lane & 15);
                    int col = n0 + jp * 16 + (lane >> 4) * 8;
                    unsigned off = (unsigned)(row * 136 + col) * 2u;
                    unsigned r0, r1, r2, r3;
                    ldsm_x4_t(r0, r1, r2, r3, sBh + bOff + off);
                    bh[2*jp][0] = r0; bh[2*jp][1] = r1;
                    bh[2*jp+1][0] = r2; bh[2*jp+1][1] = r3;
                    ldsm_x4_t(r0, r1, r2, r3, sBl + bOff + off);
                    bl[2*jp][0] = r0; bl[2*jp][1] = r1;
                    bl[2*jp+1][0] = r2; bl[2*jp+1][1] = r3;
                }
            }
            #pragma unroll
            for (int j = 0; j < 4; j++) {
                #pragma unroll
                for (int i = 0; i < 4; i++) {
                    mma16816(acc[i][j], ah[i], bh[j]);
                    mma16816(acc[i][j], ah[i], bl[j]);
                    mma16816(acc[i][j], al[i], bh[j]);
                }
            }
        }

        if (it + 1 < total) store_stage(st ^ 1);
        __syncthreads();
    }

    // ---- epilogue ----
    #pragma unroll
    for (int i = 0; i < 4; i++) {
        long r0 = (long)(by * 128 + m0 + i * 16 + g);
        long r1 = r0 + 8;
        #pragma unroll
        for (int j = 0; j < 4; j++) {
            long c = (long)(bx * 128 + n0 + j * 8 + 2 * t);
            if (ACC) {
                C[r0 * N + c]     += acc[i][j][0];
                C[r0 * N + c + 1] += acc[i][j][1];
                C[r1 * N + c]     += acc[i][j][2];
                C[r1 * N + c + 1] += acc[i][j][3];
            } else {
                *(float2*)&C[r0 * N + c] = make_float2(acc[i][j][0], acc[i][j][1]);
                *(float2*)&C[r1 * N + c] = make_float2(acc[i][j][2], acc[i][j][3]);
            }
        }
    }
}

// ---------------- launch ----------------
extern "C" void kernel_launch(void* const* d_in, const int* in_sizes, int n_in,
                              void* d_out, int out_size) {
    const int*   idx       = (const int*)  d_in[0];
    const float* cons      = (const float*)d_in[1];
    const float* tok_emb   = (const float*)d_in[2];
    const float* head_g    = (const float*)d_in[3];
    const float* cv_w1     = (const float*)d_in[4];
    const float* cv_b1     = (const float*)d_in[5];
    const float* cv_w2     = (const float*)d_in[6];
    const float* cv_b2     = (const float*)d_in[7];
    const float* tension_w = (const float*)d_in[8];
    const float* ln_attn   = (const float*)d_in[9];
    const float* ln_pf     = (const float*)d_in[10];
    const float* ln_moe    = (const float*)d_in[11];
    const float* ln_f      = (const float*)d_in[12];
    const float* wq        = (const float*)d_in[13];
    const float* wk        = (const float*)d_in[14];
    const float* wv        = (const float*)d_in[15];
    const float* wo        = (const float*)d_in[16];
    const float* pf_gate   = (const float*)d_in[17];
    const float* pf_up     = (const float*)d_in[18];
    const float* pf_down   = (const float*)d_in[19];
    const float* e_gate    = (const float*)d_in[20];
    const float* e_up      = (const float*)d_in[21];
    const float* e_down    = (const float*)d_in[22];
    const float* router_w  = (const float*)d_in[23];
    const float* router_b  = (const float*)d_in[24];
    float* out = (float*)d_out;

    float *xp, *hp, *qp, *kp, *vp, *aop, *ebp, *cvp, *twp;
    int* tip;
    cudaGetSymbolAddress((void**)&xp,  g_x);
    cudaGetSymbolAddress((void**)&hp,  g_h);
    cudaGetSymbolAddress((void**)&qp,  g_q);
    cudaGetSymbolAddress((void**)&kp,  g_k);
    cudaGetSymbolAddress((void**)&vp,  g_v);
    cudaGetSymbolAddress((void**)&aop, g_ao);
    cudaGetSymbolAddress((void**)&ebp, g_eb);
    cudaGetSymbolAddress((void**)&cvp, g_cv);
    cudaGetSymbolAddress((void**)&twp, g_tw);
    cudaGetSymbolAddress((void**)&tip, g_ti);

    // opt-in to >48KB dynamic smem (idempotent; not a capture op)
    constexpr int SMN = smem_bytes<false>();   // 75,776
    constexpr int SMT = smem_bytes<true>();    // 81,920
    cudaFuncSetAttribute(gemm_kernel<false, false, 0>, cudaFuncAttributeMaxDynamicSharedMemorySize, SMN);
    cudaFuncSetAttribute(gemm_kernel<true,  false, 0>, cudaFuncAttributeMaxDynamicSharedMemorySize, SMN);
    cudaFuncSetAttribute(gemm_kernel<false, true,  0>, cudaFuncAttributeMaxDynamicSharedMemorySize, SMT);
    cudaFuncSetAttribute(gemm_kernel<false, false, 1>, cudaFuncAttributeMaxDynamicSharedMemorySize, SMN);
    cudaFuncSetAttribute(gemm_kernel<true,  false, 2>, cudaFuncAttributeMaxDynamicSharedMemorySize, SMN);

    float* tens = out + (long)2 * ROWS * VV;   // output tail: tensions (L, B, T)
    float* b1p = ebp;                           // PureField gate buffer
    float* b2p = ebp + (long)ROWS * DII;        // PureField up buffer

    embed_kernel<<<(ROWS * DD + 255) / 256, 256>>>(idx, tok_emb, xp);
    cv_kernel<<<1, 256>>>(cons, cv_w1, cv_b1, cv_w2, cv_b2, cvp);

    const dim3 g768 (DD  / 128, ROWS / 128, 1);   // (6, 32)
    const dim3 gkv  (256 / 128, ROWS / 128, 2);   // paired K & V
    const dim3 gff  (DII / 128, ROWS / 128, 2);   // paired gate & up
    const dim3 gegu (DII / 128, ROWS / 128, 6);   // MoE 3 experts x gate/up
    const dim3 gdn  (DD  / 128, ROWS / 128, 1);   // MoE down (3 K-segments inside)

    for (int l = 0; l < LL; l++) {
        // ---- attention block ----
        rms_kernel<<<ROWS, 256>>>(xp, ln_attn + (long)l * DD, hp);
        gemm_kernel<false, false, 0><<<g768, 256, SMN>>>(hp, wq + (long)l * DD * 768, qp,
                                                 nullptr, nullptr, ROWS, 768, DD, nullptr, 0);
        gemm_kernel<false, false, 0><<<gkv, 256, SMN>>>(hp, wk + (long)l * DD * 256, kp,
                                                wv + (long)l * DD * 256, vp,
                                                ROWS, 256, DD, nullptr, 0);
        attn_kernel<<<dim3(TT / 64, NHH, BB), 64>>>(qp, kp, vp, aop);
        gemm_kernel<true, false, 0><<<g768, 256, SMN>>>(aop, wo + (long)l * 768 * DD, xp,
                                                nullptr, nullptr, ROWS, DD, 768, nullptr, 0);

        // ---- PureField FFN + tension ----
        rms_kernel<<<ROWS, 256>>>(xp, ln_pf + (long)l * DD, hp);
        gemm_kernel<false, false, 0><<<gff, 256, SMN>>>(hp, pf_gate + (long)l * DD * DII, b1p,
                                                pf_up + (long)l * DD * DII, b2p,
                                                ROWS, DII, DD, nullptr, 0);
        swiglu_kernel<<<ROWS, 256>>>(b1p, b2p, b1p, tens + (long)l * ROWS);
        gemm_kernel<true, false, 0><<<g768, 256, SMN>>>(b1p, pf_down + (long)l * DII * DD, xp,
                                                nullptr, nullptr, ROWS, DD, DII, nullptr, 0);

        // ---- consciousness-state residual (previous layer's tension) ----
        if (l > 0)
            csadd_kernel<<<ROWS, 256>>>(xp, tens + (long)(l - 1) * ROWS, tension_w);

        // ---- MoE (top-3 of 10, routed per batch element) ----
        rms_kernel<<<ROWS, 256>>>(xp, ln_moe + (long)l * DD, hp);
        router_kernel<<<1, 32>>>(cvp, router_w + (long)l * 100, router_b + (long)l * 10,
                                 twp, tip);
        gemm_kernel<false, false, 1><<<gegu, 256, SMN>>>(hp, e_gate + (long)l * 10 * DD * DII,
                                                ebp, e_up + (long)l * 10 * DD * DII, nullptr,
                                                ROWS, DII, DD, tip, (long)DD * DII);
        swiglu_moe_kernel<<<dim3(ROWS, 3), 256>>>(ebp, twp);
        gemm_kernel<true, false, 2><<<gdn, 256, SMN>>>(ebp, e_down + (long)l * 10 * DII * DD,
                                                xp, nullptr, nullptr, ROWS, DD, DII,
                                                tip, (long)DII * DD);
    }

    // ---- final norm + tied heads (paired) ----
    rms_kernel<<<ROWS, 256>>>(xp, ln_f, hp);
    const dim3 gv(VV / 128, ROWS / 128, 2);       // (250, 32, 2)
    gemm_kernel<false, true, 0><<<gv, 256, SMT>>>(hp, tok_emb, out,
                                          head_g, out + (long)ROWS * VV,
                                          ROWS, VV, DD, nullptr, 0);
}

// round 5
// speedup vs baseline: 2.3503x; 1.1587x over previous
#include <cuda_runtime.h>
#include <cuda_bf16.h>
#include <math.h>

typedef __nv_bfloat16 bf16;

// ---------------- dims ----------------
#define BB   2
#define TT   2048
#define DD   768
#define NHH  12
#define NKVV 4
#define HDD  64
#define LL   6
#define VV   32000
#define DII  1536
#define NCC  64
#define CDD  128
#define ROWS (BB*TT)          // 4096
#define GATE_STRENGTH 0.001f
#define EXN  ((long)DD*DII)   // expert matrix elements = 1,179,648

// ---------------- fp32 scratch ----------------
__device__ float g_x [ROWS*DD];
__device__ float g_q [ROWS*NHH*HDD];
__device__ float g_k [ROWS*NKVV*HDD];
__device__ float g_v [ROWS*NKVV*HDD];
__device__ float g_eb[6L*ROWS*DII];    // gate/up GEMM outputs (PF uses slots 0,1)
__device__ float g_cv[BB*10];
__device__ float g_tw[LL*BB*3];
__device__ int   g_ti[LL*BB*3];

// ---------------- bf16 hi/lo activation planes ----------------
__device__ bf16 g_h_h [ROWS*DD],        g_h_l [ROWS*DD];
__device__ bf16 g_ao_h[ROWS*NHH*HDD],   g_ao_l[ROWS*NHH*HDD];
__device__ bf16 g_hd_h[ROWS*DII],       g_hd_l[ROWS*DII];       // PF hidden
__device__ bf16 g_mh_h[3L*ROWS*DII],    g_mh_l[3L*ROWS*DII];    // MoE hidden

// ---------------- bf16 hi/lo weight planes ----------------
__device__ bf16 g_wq_h[6L*768*768],  g_wq_l[6L*768*768];
__device__ bf16 g_wk_h[6L*768*256],  g_wk_l[6L*768*256];
__device__ bf16 g_wv_h[6L*768*256],  g_wv_l[6L*768*256];
__device__ bf16 g_wo_h[6L*768*768],  g_wo_l[6L*768*768];
__device__ bf16 g_pg_h[6L*768*1536], g_pg_l[6L*768*1536];
__device__ bf16 g_pu_h[6L*768*1536], g_pu_l[6L*768*1536];
__device__ bf16 g_pd_h[6L*1536*768], g_pd_l[6L*1536*768];
__device__ bf16 g_em_h[(long)VV*DD], g_em_l[(long)VV*DD];
__device__ bf16 g_hg_h[(long)VV*DD], g_hg_l[(long)VV*DD];
__device__ bf16 g_eg_h[36L*DD*DII],  g_eg_l[36L*DD*DII];
__device__ bf16 g_eu_h[36L*DD*DII],  g_eu_l[36L*DD*DII];
__device__ bf16 g_ed_h[36L*DD*DII],  g_ed_l[36L*DD*DII];

// ---------------- helpers ----------------
__device__ __forceinline__ float block_reduce_sum_256(float v) {
    __shared__ float red[8];
    int t = threadIdx.x;
    #pragma unroll
    for (int off = 16; off; off >>= 1) v += __shfl_xor_sync(0xffffffffu, v, off);
    if ((t & 31) == 0) red[t >> 5] = v;
    __syncthreads();
    float tot = 0.f;
    #pragma unroll
    for (int i = 0; i < 8; i++) tot += red[i];
    return tot;
}

__device__ __forceinline__ void split1(float f, bf16& h, bf16& l) {
    h = __float2bfloat16_rn(f);
    l = __float2bfloat16_rn(f - __bfloat162float(h));
}

__device__ __forceinline__ void split2(float f0, float f1, unsigned& hi, unsigned& lo) {
    __nv_bfloat162 h = __floats2bfloat162_rn(f0, f1);
    float r0 = f0 - __bfloat162float(__low2bfloat16(h));
    float r1 = f1 - __bfloat162float(__high2bfloat16(h));
    __nv_bfloat162 l = __floats2bfloat162_rn(r0, r1);
    hi = *(unsigned*)&h;
    lo = *(unsigned*)&l;
}

__device__ __forceinline__ void mma16816(float* c, const unsigned* a, const unsigned* b) {
    asm volatile(
        "mma.sync.aligned.m16n8k16.row.col.f32.bf16.bf16.f32 "
        "{%0,%1,%2,%3}, {%4,%5,%6,%7}, {%8,%9}, {%0,%1,%2,%3};\n"
        : "+f"(c[0]), "+f"(c[1]), "+f"(c[2]), "+f"(c[3])
        : "r"(a[0]), "r"(a[1]), "r"(a[2]), "r"(a[3]), "r"(b[0]), "r"(b[1]));
}

__device__ __forceinline__ void ldsm_x4(unsigned& r0, unsigned& r1, unsigned& r2,
                                        unsigned& r3, unsigned addr) {
    asm volatile("ldmatrix.sync.aligned.m8n8.x4.shared.b16 {%0,%1,%2,%3}, [%4];\n"
                 : "=r"(r0), "=r"(r1), "=r"(r2), "=r"(r3) : "r"(addr));
}

__device__ __forceinline__ void ldsm_x4_t(unsigned& r0, unsigned& r1, unsigned& r2,
                                          unsigned& r3, unsigned addr) {
    asm volatile("ldmatrix.sync.aligned.m8n8.x4.trans.shared.b16 {%0,%1,%2,%3}, [%4];\n"
                 : "=r"(r0), "=r"(r1), "=r"(r2), "=r"(r3) : "r"(addr));
}

__device__ __forceinline__ void cp16(unsigned dst, const void* src) {
    asm volatile("cp.async.cg.shared.global [%0], [%1], 16;\n" :: "r"(dst), "l"(src));
}
__device__ __forceinline__ void cp_commit() { asm volatile("cp.async.commit_group;\n"); }
__device__ __forceinline__ void cp_wait0()  { asm volatile("cp.async.wait_group 0;\n"); }

// ---------------- weight converters ----------------
__global__ void convw_kernel(const float* __restrict__ s, bf16* __restrict__ hi,
                             bf16* __restrict__ lo, long n) {
    long i = ((long)blockIdx.x * blockDim.x + threadIdx.x) * 4;
    if (i < n) {
        float4 v = *(const float4*)(s + i);
        unsigned h0, l0, h1, l1;
        split2(v.x, v.y, h0, l0);
        split2(v.z, v.w, h1, l1);
        *(uint2*)&hi[i] = make_uint2(h0, h1);
        *(uint2*)&lo[i] = make_uint2(l0, l1);
    }
}

// selected-expert conversion: grid (EXN/1024, 36, 3)
__global__ void convexp_kernel(const float* __restrict__ eg, const float* __restrict__ eu,
                               const float* __restrict__ ed,
                               bf16* gh, bf16* gl, bf16* uh, bf16* ul,
                               bf16* dh, bf16* dl, const int* __restrict__ ti) {
    const int slot = blockIdx.y, mat = blockIdx.z;
    const int l = slot / 6, e = ti[slot];
    long i = ((long)blockIdx.x * 256 + threadIdx.x) * 4;
    if (i >= EXN) return;
    const float* src; bf16 *hi, *lo;
    if (mat == 0)      { src = eg; hi = gh; lo = gl; }
    else if (mat == 1) { src = eu; hi = uh; lo = ul; }
    else               { src = ed; hi = dh; lo = dl; }
    src += ((long)l * 10 + e) * EXN + i;
    hi  += (long)slot * EXN + i;
    lo  += (long)slot * EXN + i;
    float4 v = *(const float4*)src;
    unsigned h0, l0, h1, l1;
    split2(v.x, v.y, h0, l0);
    split2(v.z, v.w, h1, l1);
    *(uint2*)hi = make_uint2(h0, h1);
    *(uint2*)lo = make_uint2(l0, l1);
}

// ---------------- embedding ----------------
__global__ void embed_kernel(const int* __restrict__ idx,
                             const float* __restrict__ emb,
                             float* __restrict__ x) {
    long i = (long)blockIdx.x * blockDim.x + threadIdx.x;
    if (i < (long)ROWS * DD) {
        long r = i / DD, c = i % DD;
        x[i] = emb[(long)idx[r] * DD + c];
    }
}

// ---------------- consciousness vector (tiny MLP) ----------------
__global__ void cv_kernel(const float* __restrict__ cs,
                          const float* __restrict__ w1, const float* __restrict__ b1,
                          const float* __restrict__ w2, const float* __restrict__ b2,
                          float* __restrict__ cv) {
    __shared__ float pooled[BB][CDD];
    __shared__ float h1[BB][64];
    int t = threadIdx.x;  // 256 threads
    {
        int b = t / CDD, c = t % CDD;
        float s = 0.f;
        for (int n = 0; n < NCC; n++)
            s += cs[((long)b * NCC + n) * CDD + c];
        pooled[b][c] = s * (1.f / NCC);
    }
    __syncthreads();
    if (t < BB * 64) {
        int b = t / 64, j = t % 64;
        float z = b1[j];
        for (int c = 0; c < CDD; c++) z += pooled[b][c] * w1[c * 64 + j];
        float z3 = z * z * z;
        h1[b][j] = 0.5f * z * (1.f + tanhf(0.7978845608028654f * (z + 0.044715f * z3)));
    }
    __syncthreads();
    if (t < BB * 10) {
        int b = t / 10, i = t % 10;
        float z = b2[i];
        for (int j = 0; j < 64; j++) z += h1[b][j] * w2[j * 10 + i];
        cv[b * 10 + i] = 1.f / (1.f + expf(-z));
    }
}

// ---------------- routers for all layers ----------------
__global__ void router_all_kernel(const float* __restrict__ cv,
                                  const float* __restrict__ W,
                                  const float* __restrict__ bias,
                                  float* __restrict__ tw, int* __restrict__ ti) {
    int l = blockIdx.x;
    int b = threadIdx.x;
    if (b >= BB) return;
    const float* Wl = W + (long)l * 100;
    const float* bl = bias + (long)l * 10;
    float lg[10];
    float mx = -1e30f;
    for (int i = 0; i < 10; i++) {
        float z = bl[i];
        for (int j = 0; j < 10; j++) z += cv[b * 10 + j] * Wl[j * 10 + i];
        lg[i] = z;
        mx = fmaxf(mx, z);
    }
    float se = 0.f;
    for (int i = 0; i < 10; i++) { lg[i] = expf(lg[i] - mx); se += lg[i]; }
    for (int i = 0; i < 10; i++) lg[i] /= se;
    float wsum = 0.f;
    int base = l * 6 + b * 3;
    for (int kk = 0; kk < 3; kk++) {
        int bi = 0; float bv = -1.f;
        for (int i = 0; i < 10; i++) if (lg[i] > bv) { bv = lg[i]; bi = i; }
        ti[base + kk] = bi; tw[base + kk] = bv; wsum += bv;
        lg[bi] = -2.f;
    }
    for (int kk = 0; kk < 3; kk++) tw[base + kk] /= wsum;
}

// ---------------- RMSNorm -> bf16 hi/lo planes ----------------
__global__ void __launch_bounds__(256) rms_kernel(const float* __restrict__ x,
                                                  const float* __restrict__ w,
                                                  bf16* __restrict__ oh,
                                                  bf16* __restrict__ ol) {
    int row = blockIdx.x, t = threadIdx.x;
    const float* xr = x + (long)row * DD;
    float v0 = xr[t], v1 = xr[t + 256], v2 = xr[t + 512];
    float tot = block_reduce_sum_256(v0 * v0 + v1 * v1 + v2 * v2);
    float s = rsqrtf(tot * (1.f / DD) + 1e-6f);
    bf16* ohr = oh + (long)row * DD;
    bf16* olr = ol + (long)row * DD;
    split1(v0 * s * w[t],       ohr[t],       olr[t]);
    split1(v1 * s * w[t + 256], ohr[t + 256], olr[t + 256]);
    split1(v2 * s * w[t + 512], ohr[t + 512], olr[t + 512]);
}

// ---------------- SwiGLU (+ tension) -> bf16 planes ----------------
__global__ void __launch_bounds__(256) swiglu_kernel(const float* __restrict__ g,
                                                     const float* __restrict__ u,
                                                     bf16* __restrict__ oh,
                                                     bf16* __restrict__ ol,
                                                     float* __restrict__ tension) {
    int row = blockIdx.x, t = threadIdx.x;
    const float* gr = g + (long)row * DII;
    const float* ur = u + (long)row * DII;
    bf16* ohr = oh + (long)row * DII;
    bf16* olr = ol + (long)row * DII;
    float sum = 0.f;
    #pragma unroll
    for (int j = 0; j < 6; j++) {
        int c = t + j * 256;
        float a = gr[c], bv = ur[c];
        float hv = (a / (1.f + __expf(-a))) * bv;
        split1(hv, ohr[c], olr[c]);
        sum += hv;
    }
    float tot = block_reduce_sum_256(sum);
    if (t == 0) tension[row] = tanhf(tot * (1.f / DII));
}

// ---------------- MoE SwiGLU (folds router weight) -> bf16 planes --------------
__global__ void __launch_bounds__(256) swiglu_moe_kernel(const float* __restrict__ buf,
                                                         const float* __restrict__ tw,
                                                         bf16* __restrict__ mh,
                                                         bf16* __restrict__ ml) {
    int row = blockIdx.x, e = blockIdx.y, t = threadIdx.x;
    int b = row / TT;
    float scale = tw[b * 3 + e];
    const float* gr = buf + (long)(2 * e) * ROWS * DII + (long)row * DII;
    const float* ur = buf + (long)(2 * e + 1) * ROWS * DII + (long)row * DII;
    bf16* ohr = mh + (long)e * ROWS * DII + (long)row * DII;
    bf16* olr = ml + (long)e * ROWS * DII + (long)row * DII;
    #pragma unroll
    for (int j = 0; j < 6; j++) {
        int c = t + j * 256;
        float a = gr[c], bv = ur[c];
        split1((a / (1.f + __expf(-a))) * bv * scale, ohr[c], olr[c]);
    }
}

// ---------------- consciousness-state residual add ----------------
__global__ void __launch_bounds__(256) csadd_kernel(float* __restrict__ x,
                                                    const float* __restrict__ tension,
                                                    const float* __restrict__ tw) {
    int row = blockIdx.x, t = threadIdx.x;
    float ten = tension[row] * GATE_STRENGTH;
    float* xr = x + (long)row * DD;
    xr[t]       += ten * tw[t];
    xr[t + 256] += ten * tw[t + 256];
    xr[t + 512] += ten * tw[t + 512];
}

// ---------------- flash-style causal attention (fp32, GQA) ----------------
__global__ void __launch_bounds__(64) attn_kernel(const float* __restrict__ q,
                                                  const float* __restrict__ k,
                                                  const float* __restrict__ v,
                                                  bf16* __restrict__ oh,
                                                  bf16* __restrict__ ol) {
    const int q0 = blockIdx.x * 64;
    const int h  = blockIdx.y;
    const int b  = blockIdx.z;
    const int t  = threadIdx.x;
    const int qg = q0 + t;
    const int kvh = h / (NHH / NKVV);

    __shared__ float Ks[64][64];
    __shared__ float Vs[64][64];

    float qreg[64], acc[64];
    const float* qp = q + ((long)(b * TT + qg) * NHH + h) * HDD;
    #pragma unroll
    for (int d = 0; d < 64; d++) { qreg[d] = qp[d]; acc[d] = 0.f; }
    float lsum = 0.f;

    for (int s0 = 0; s0 <= q0; s0 += 64) {
        __syncthreads();
        #pragma unroll 8
        for (int r = 0; r < 64; r++) {
            long base = ((long)(b * TT + s0 + r) * NKVV + kvh) * HDD + t;
            Ks[r][t] = k[base];
            Vs[r][t] = v[base];
        }
        __syncthreads();
        int kmax = min(64, qg - s0 + 1);
        for (int kk = 0; kk < kmax; kk++) {
            float s = 0.f;
            #pragma unroll
            for (int d = 0; d < 64; d++) s += qreg[d] * Ks[kk][d];
            float p = __expf(s * 0.125f);
            lsum += p;
            #pragma unroll
            for (int d = 0; d < 64; d++) acc[d] += p * Vs[kk][d];
        }
    }
    float inv = 1.f / lsum;
    long base = ((long)(b * TT + qg) * NHH + h) * HDD;
    #pragma unroll
    for (int d = 0; d < 64; d += 2) {
        unsigned hi, lo;
        split2(acc[d] * inv, acc[d + 1] * inv, hi, lo);
        *(unsigned*)&oh[base + d] = hi;
        *(unsigned*)&ol[base + d] = lo;
    }
}

// ---------------- tensor-core GEMM: bf16 hi/lo planes, cp.async, 2 CTA/SM ------
// C(MxN) = [C +] Ahi@Bhi + Ahi@Blo + Alo@Bhi   (fp32 accum)
// MODE 0: plain; optional pair (B2,C2) via blockIdx.z.
// MODE 1: MoE gate/up: z in [0,6): kexp=z>>1; plane = (z&1 ? B2 : B) +
//         (b*3+kexp)*sstride; C += z*ROWS*N.
// MODE 2: MoE down: 3 K-segments; A seg s at +s*ROWS*K; B seg s at +(b*3+s)*sstride.
template<bool ACC, bool TRANSB, int MODE>
__global__ void __launch_bounds__(256, 2) gemm_bf16(
    const bf16* __restrict__ Ah, const bf16* __restrict__ Al,
    const bf16* __restrict__ Bh, const bf16* __restrict__ Bl,
    float* __restrict__ C,
    const bf16* __restrict__ B2h, const bf16* __restrict__ B2l, float* __restrict__ C2,
    int M, int N, int K, long sstride)
{
    const int bx = blockIdx.x, by = blockIdx.y;
    const int bb = (by * 128) / TT;              // batch (tiles never straddle)
    if (MODE == 0) {
        if (B2h != nullptr && blockIdx.z == 1) { Bh = B2h; Bl = B2l; C = C2; }
    } else if (MODE == 1) {
        const int z = blockIdx.z, kexp = z >> 1;
        long off = (long)(bb * 3 + kexp) * sstride;
        if (z & 1) { Bh = B2h + off; Bl = B2l + off; }
        else       { Bh = Bh  + off; Bl = Bl  + off; }
        C += (long)z * ROWS * N;
    }
    const bf16 *Bsh[3], *Bsl[3];
    if (MODE == 2) {
        #pragma unroll
        for (int s = 0; s < 3; s++) {
            long off = (long)(bb * 3 + s) * sstride;
            Bsh[s] = Bh + off; Bsl[s] = Bl + off;
        }
    }

    extern __shared__ bf16 sm[];
    constexpr int ASZ2 = 128 * 40;
    constexpr int BSZ2 = TRANSB ? 128 * 40 : 32 * 136;
    bf16* smAh = sm;                 // [2][ASZ2]
    bf16* smAl = smAh + 2 * ASZ2;
    bf16* smBh = smAl + 2 * ASZ2;    // [2][BSZ2]
    bf16* smBl = smBh + 2 * BSZ2;

    const unsigned uAh = (unsigned)__cvta_generic_to_shared(smAh);
    const unsigned uAl = (unsigned)__cvta_generic_to_shared(smAl);
    const unsigned uBh = (unsigned)__cvta_generic_to_shared(smBh);
    const unsigned uBl = (unsigned)__cvta_generic_to_shared(smBl);

    const int tid = threadIdx.x;
    const int wid = tid >> 5, lane = tid & 31;
    const int g = lane >> 2, t = lane & 3;
    const int m0 = (wid & 1) * 64, n0 = (wid >> 1) * 32;

    const int arow = tid >> 1, acb = (tid & 1) * 16;
    const int kr = tid >> 3,  nb = (tid & 7) * 16;

    const int kIters = K >> 5;
    const int total  = (MODE == 2 ? 3 : 1) * kIters;

    auto issue = [&](int it, int st) {
        const int seg = (MODE == 2) ? it / kIters : 0;
        const int k0  = ((MODE == 2) ? (it % kIters) : it) * 32;
        long aoff = ((MODE == 2) ? (long)seg * ROWS * K : 0)
                  + (long)(by * 128 + arow) * K + k0 + acb;
        unsigned d = uAh + (unsigned)(st * ASZ2 + arow * 40 + acb) * 2u;
        cp16(d, Ah + aoff);       cp16(d + 16, Ah + aoff + 8);
        d = uAl + (unsigned)(st * ASZ2 + arow * 40 + acb) * 2u;
        cp16(d, Al + aoff);       cp16(d + 16, Al + aoff + 8);
        if (TRANSB) {
            long boff = (long)(bx * 128 + arow) * K + k0 + acb;
            d = uBh + (unsigned)(st * BSZ2 + arow * 40 + acb) * 2u;
            cp16(d, Bh + boff);   cp16(d + 16, Bh + boff + 8);
            d = uBl + (unsigned)(st * BSZ2 + arow * 40 + acb) * 2u;
            cp16(d, Bl + boff);   cp16(d + 16, Bl + boff + 8);
        } else {
            const bf16* bh = (MODE == 2) ? Bsh[seg] : Bh;
            const bf16* bl = (MODE == 2) ? Bsl[seg] : Bl;
            long boff = (long)(k0 + kr) * N + bx * 128 + nb;
            d = uBh + (unsigned)(st * BSZ2 + kr * 136 + nb) * 2u;
            cp16(d, bh + boff);   cp16(d + 16, bh + boff + 8);
            d = uBl + (unsigned)(st * BSZ2 + kr * 136 + nb) * 2u;
            cp16(d, bl + boff);   cp16(d + 16, bl + boff + 8);
        }
        cp_commit();
    };

    float acc[4][4][4];
    #pragma unroll
    for (int i = 0; i < 4; i++)
        #pragma unroll
        for (int j = 0; j < 4; j++)
            #pragma unroll
            for (int e = 0; e < 4; e++) acc[i][j][e] = 0.f;

    issue(0, 0);

    for (int it = 0; it < total; it++) {
        const int st = it & 1;
        cp_wait0();
        __syncthreads();
        if (it + 1 < total) issue(it + 1, st ^ 1);

        const unsigned aO = (unsigned)(st * ASZ2) * 2u;
        const unsigned bO = (unsigned)(st * BSZ2) * 2u;
        #pragma unroll
        for (int ks = 0; ks < 2; ks++) {
            const int kk = ks * 16;
            unsigned ah[4][4], al[4][4];
            #pragma unroll
            for (int i = 0; i < 4; i++) {
                int row = m0 + i * 16 + (lane & 15);
                int col = kk + (lane >> 4) * 8;
                unsigned off = (unsigned)(row * 40 + col) * 2u;
                ldsm_x4(ah[i][0], ah[i][1], ah[i][2], ah[i][3], uAh + aO + off);
                ldsm_x4(al[i][0], al[i][1], al[i][2], al[i][3], uAl + aO + off);
            }
            unsigned bh[4][2], bl[4][2];
            if (TRANSB) {
                #pragma unroll
                for (int jp = 0; jp < 2; jp++) {
                    int row = n0 + jp * 16 + (lane & 15);
                    int col = kk + (lane >> 4) * 8;
                    unsigned off = (unsigned)(row * 40 + col) * 2u;
                    unsigned r0, r1, r2, r3;
                    ldsm_x4(r0, r1, r2, r3, uBh + bO + off);
                    bh[2*jp][0] = r0; bh[2*jp+1][0] = r1;
                    bh[2*jp][1] = r2; bh[2*jp+1][1] = r3;
                    ldsm_x4(r0, r1, r2, r3, uBl + bO + off);
                    bl[2*jp][0] = r0; bl[2*jp+1][0] = r1;
                    bl[2*jp][1] = r2; bl[2*jp+1][1] = r3;
                }
            } else {
                #pragma unroll
                for (int jp = 0; jp < 2; jp++) {
                    int row = kk + (lane & 15);
                    int col = n0 + jp * 16 + (lane >> 4) * 8;
                    unsigned off = (unsigned)(row * 136 + col) * 2u;
                    unsigned r0, r1, r2, r3;
                    ldsm_x4_t(r0, r1, r2, r3, uBh + bO + off);
                    bh[2*jp][0] = r0; bh[2*jp][1] = r1;
                    bh[2*jp+1][0] = r2; bh[2*jp+1][1] = r3;
                    ldsm_x4_t(r0, r1, r2, r3, uBl + bO + off);
                    bl[2*jp][0] = r0; bl[2*jp][1] = r1;
                    bl[2*jp+1][0] = r2; bl[2*jp+1][1] = r3;
                }
            }
            #pragma unroll
            for (int j = 0; j < 4; j++) {
                #pragma unroll
                for (int i = 0; i < 4; i++) {
                    mma16816(acc[i][j], ah[i], bh[j]);
                    mma16816(acc[i][j], ah[i], bl[j]);
                    mma16816(acc[i][j], al[i], bh[j]);
                }
            }
        }
    }

    // ---- epilogue ----
    #pragma unroll
    for (int i = 0; i < 4; i++) {
        long r0 = (long)(by * 128 + m0 + i * 16 + g);
        long r1 = r0 + 8;
        #pragma unroll
        for (int j = 0; j < 4; j++) {
            long c = (long)(bx * 128 + n0 + j * 8 + 2 * t);
            if (ACC) {
                C[r0 * N + c]     += acc[i][j][0];
                C[r0 * N + c + 1] += acc[i][j][1];
                C[r1 * N + c]     += acc[i][j][2];
                C[r1 * N + c + 1] += acc[i][j][3];
            } else {
                *(float2*)&C[r0 * N + c] = make_float2(acc[i][j][0], acc[i][j][1]);
                *(float2*)&C[r1 * N + c] = make_float2(acc[i][j][2], acc[i][j][3]);
            }
        }
    }
}

// smem sizes
constexpr int SMN = (4 * 128 * 40 + 4 * 32 * 136) * 2;   // 75,776 B
constexpr int SMT = (4 * 128 * 40 + 4 * 128 * 40) * 2;   // 81,920 B

// ---------------- launch ----------------
extern "C" void kernel_launch(void* const* d_in, const int* in_sizes, int n_in,
                              void* d_out, int out_size) {
    const int*   idx       = (const int*)  d_in[0];
    const float* cons      = (const float*)d_in[1];
    const float* tok_emb   = (const float*)d_in[2];
    const float* head_g    = (const float*)d_in[3];
    const float* cv_w1     = (const float*)d_in[4];
    const float* cv_b1     = (const float*)d_in[5];
    const float* cv_w2     = (const float*)d_in[6];
    const float* cv_b2     = (const float*)d_in[7];
    const float* tension_w = (const float*)d_in[8];
    const float* ln_attn   = (const float*)d_in[9];
    const float* ln_pf     = (const float*)d_in[10];
    const float* ln_moe    = (const float*)d_in[11];
    const float* ln_f      = (const float*)d_in[12];
    const float* wq        = (const float*)d_in[13];
    const float* wk        = (const float*)d_in[14];
    const float* wv        = (const float*)d_in[15];
    const float* wo        = (const float*)d_in[16];
    const float* pf_gate   = (const float*)d_in[17];
    const float* pf_up     = (const float*)d_in[18];
    const float* pf_down   = (const float*)d_in[19];
    const float* e_gate    = (const float*)d_in[20];
    const float* e_up      = (const float*)d_in[21];
    const float* e_down    = (const float*)d_in[22];
    const float* router_w  = (const float*)d_in[23];
    const float* router_b  = (const float*)d_in[24];
    float* out = (float*)d_out;

    // scratch addresses
    float *xp, *qp, *kp, *vp, *ebp, *cvp, *twp;  int* tip;
    bf16 *hh, *hl, *aoh, *aol, *hdh, *hdl, *mhh, *mhl;
    bf16 *wqh, *wql, *wkh, *wkl, *wvh, *wvl, *woh, *wol;
    bf16 *pgh, *pgl, *puh, *pul, *pdh, *pdl;
    bf16 *emh, *eml, *hgh, *hgl;
    bf16 *egh, *egl, *euh, *eul, *edh, *edl;
    cudaGetSymbolAddress((void**)&xp,  g_x);
    cudaGetSymbolAddress((void**)&qp,  g_q);
    cudaGetSymbolAddress((void**)&kp,  g_k);
    cudaGetSymbolAddress((void**)&vp,  g_v);
    cudaGetSymbolAddress((void**)&ebp, g_eb);
    cudaGetSymbolAddress((void**)&cvp, g_cv);
    cudaGetSymbolAddress((void**)&twp, g_tw);
    cudaGetSymbolAddress((void**)&tip, g_ti);
    cudaGetSymbolAddress((void**)&hh,  g_h_h);  cudaGetSymbolAddress((void**)&hl,  g_h_l);
    cudaGetSymbolAddress((void**)&aoh, g_ao_h); cudaGetSymbolAddress((void**)&aol, g_ao_l);
    cudaGetSymbolAddress((void**)&hdh, g_hd_h); cudaGetSymbolAddress((void**)&hdl, g_hd_l);
    cudaGetSymbolAddress((void**)&mhh, g_mh_h); cudaGetSymbolAddress((void**)&mhl, g_mh_l);
    cudaGetSymbolAddress((void**)&wqh, g_wq_h); cudaGetSymbolAddress((void**)&wql, g_wq_l);
    cudaGetSymbolAddress((void**)&wkh, g_wk_h); cudaGetSymbolAddress((void**)&wkl, g_wk_l);
    cudaGetSymbolAddress((void**)&wvh, g_wv_h); cudaGetSymbolAddress((void**)&wvl, g_wv_l);
    cudaGetSymbolAddress((void**)&woh, g_wo_h); cudaGetSymbolAddress((void**)&wol, g_wo_l);
    cudaGetSymbolAddress((void**)&pgh, g_pg_h); cudaGetSymbolAddress((void**)&pgl, g_pg_l);
    cudaGetSymbolAddress((void**)&puh, g_pu_h); cudaGetSymbolAddress((void**)&pul, g_pu_l);
    cudaGetSymbolAddress((void**)&pdh, g_pd_h); cudaGetSymbolAddress((void**)&pdl, g_pd_l);
    cudaGetSymbolAddress((void**)&emh, g_em_h); cudaGetSymbolAddress((void**)&eml, g_em_l);
    cudaGetSymbolAddress((void**)&hgh, g_hg_h); cudaGetSymbolAddress((void**)&hgl, g_hg_l);
    cudaGetSymbolAddress((void**)&egh, g_eg_h); cudaGetSymbolAddress((void**)&egl, g_eg_l);
    cudaGetSymbolAddress((void**)&euh, g_eu_h); cudaGetSymbolAddress((void**)&eul, g_eu_l);
    cudaGetSymbolAddress((void**)&edh, g_ed_h); cudaGetSymbolAddress((void**)&edl, g_ed_l);

    // opt-in smem (idempotent host calls, not captured)
    cudaFuncSetAttribute(gemm_bf16<false, false, 0>, cudaFuncAttributeMaxDynamicSharedMemorySize, SMN);
    cudaFuncSetAttribute(gemm_bf16<true,  false, 0>, cudaFuncAttributeMaxDynamicSharedMemorySize, SMN);
    cudaFuncSetAttribute(gemm_bf16<false, false, 1>, cudaFuncAttributeMaxDynamicSharedMemorySize, SMN);
    cudaFuncSetAttribute(gemm_bf16<true,  false, 2>, cudaFuncAttributeMaxDynamicSharedMemorySize, SMN);
    cudaFuncSetAttribute(gemm_bf16<false, true,  0>, cudaFuncAttributeMaxDynamicSharedMemorySize, SMT);

    float* tens = out + (long)2 * ROWS * VV;   // output tail: tensions (L, B, T)
    float* b1p = ebp;                          // PF gate fp32
    float* b2p = ebp + (long)ROWS * DII;       // PF up fp32

    // ---- preprocessing: embed, cv, routers, weight conversion ----
    embed_kernel<<<(ROWS * DD + 255) / 256, 256>>>(idx, tok_emb, xp);
    cv_kernel<<<1, 256>>>(cons, cv_w1, cv_b1, cv_w2, cv_b2, cvp);
    router_all_kernel<<<LL, 32>>>(cvp, router_w, router_b, twp, tip);

    auto convw = [&](const float* s, bf16* hi, bf16* lo, long n) {
        convw_kernel<<<(int)(n / 4 / 256), 256>>>(s, hi, lo, n);
    };
    convw(wq, wqh, wql, 6L * 768 * 768);
    convw(wk, wkh, wkl, 6L * 768 * 256);
    convw(wv, wvh, wvl, 6L * 768 * 256);
    convw(wo, woh, wol, 6L * 768 * 768);
    convw(pf_gate, pgh, pgl, 6L * 768 * 1536);
    convw(pf_up,   puh, pul, 6L * 768 * 1536);
    convw(pf_down, pdh, pdl, 6L * 1536 * 768);
    convw(tok_emb, emh, eml, (long)VV * DD);
    convw(head_g,  hgh, hgl, (long)VV * DD);
    convexp_kernel<<<dim3((int)(EXN / 4 / 256), 36, 3), 256>>>(
        e_gate, e_up, e_down, egh, egl, euh, eul, edh, edl, tip);

    const dim3 g768 (DD  / 128, ROWS / 128, 1);
    const dim3 gkv  (256 / 128, ROWS / 128, 2);
    const dim3 gff  (DII / 128, ROWS / 128, 2);
    const dim3 gegu (DII / 128, ROWS / 128, 6);
    const dim3 gdn  (DD  / 128, ROWS / 128, 1);

    for (int l = 0; l < LL; l++) {
        long o768  = (long)l * 768 * 768;
        long o256  = (long)l * 768 * 256;
        long o1536 = (long)l * 768 * 1536;
        long oexp  = (long)l * 6 * EXN;

        // ---- attention ----
        rms_kernel<<<ROWS, 256>>>(xp, ln_attn + (long)l * DD, hh, hl);
        gemm_bf16<false, false, 0><<<g768, 256, SMN>>>(hh, hl, wqh + o768, wql + o768, qp,
                                                       nullptr, nullptr, nullptr,
                                                       ROWS, 768, DD, 0);
        gemm_bf16<false, false, 0><<<gkv, 256, SMN>>>(hh, hl, wkh + o256, wkl + o256, kp,
                                                      wvh + o256, wvl + o256, vp,
                                                      ROWS, 256, DD, 0);
        attn_kernel<<<dim3(TT / 64, NHH, BB), 64>>>(qp, kp, vp, aoh, aol);
        gemm_bf16<true, false, 0><<<g768, 256, SMN>>>(aoh, aol, woh + o768, wol + o768, xp,
                                                      nullptr, nullptr, nullptr,
                                                      ROWS, DD, 768, 0);

        // ---- PureField FFN + tension ----
        rms_kernel<<<ROWS, 256>>>(xp, ln_pf + (long)l * DD, hh, hl);
        gemm_bf16<false, false, 0><<<gff, 256, SMN>>>(hh, hl, pgh + o1536, pgl + o1536, b1p,
                                                      puh + o1536, pul + o1536, b2p,
                                                      ROWS, DII, DD, 0);
        swiglu_kernel<<<ROWS, 256>>>(b1p, b2p, hdh, hdl, tens + (long)l * ROWS);
        gemm_bf16<true, false, 0><<<g768, 256, SMN>>>(hdh, hdl, pdh + (long)l * 1536 * 768,
                                                      pdl + (long)l * 1536 * 768, xp,
                                                      nullptr, nullptr, nullptr,
                                                      ROWS, DD, DII, 0);

        // ---- consciousness-state residual (previous layer's tension) ----
        if (l > 0)
            csadd_kernel<<<ROWS, 256>>>(xp, tens + (long)(l - 1) * ROWS, tension_w);

        // ---- MoE ----
        rms_kernel<<<ROWS, 256>>>(xp, ln_moe + (long)l * DD, hh, hl);
        gemm_bf16<false, false, 1><<<gegu, 256, SMN>>>(hh, hl, egh + oexp, egl + oexp, ebp,
                                                       euh + oexp, eul + oexp, nullptr,
                                                       ROWS, DII, DD, EXN);
        swiglu_moe_kernel<<<dim3(ROWS, 3), 256>>>(ebp, twp + (long)l * 6, mhh, mhl);
        gemm_bf16<true, false, 2><<<gdn, 256, SMN>>>(mhh, mhl, edh + oexp, edl + oexp, xp,
                                                     nullptr, nullptr, nullptr,
                                                     ROWS, DD, DII, EXN);
    }

    // ---- final norm + tied heads (paired) ----
    rms_kernel<<<ROWS, 256>>>(xp, ln_f, hh, hl);
    const dim3 gv(VV / 128, ROWS / 128, 2);
    gemm_bf16<false, true, 0><<<gv, 256, SMT>>>(hh, hl, emh, eml, out,
                                                hgh, hgl, out + (long)ROWS * VV,
                                                ROWS, VV, DD, 0);
}